// round 12
// baseline (speedup 1.0000x reference)
#include <cuda_runtime.h>
#include <cuda_bf16.h>
#include <math.h>
#include <stdint.h>

#define NODESN 40000
#define EDGESN 640000

// ---------------- static device scratch ----------------
__device__ float g_CG[15 * 125];
__device__ float g_hA[NODESN * 72];
__device__ float g_hB[NODESN * 72];
__device__ float g_hb[EDGESN * 72];     // messages, stored in CSR slot order
__device__ float g_w0[EDGESN * 24];
__device__ float g_w1[EDGESN * 120];
__device__ float g_w2[EDGESN * 120];
__device__ float2 g_w2p0[8 * 24 * 4];   // packed tf32 W2, layer0 (OD=24)
__device__ float2 g_w2p1[8 * 120 * 4];  // layer1
__device__ float2 g_w2p2[8 * 120 * 4];  // layer2
__device__ int   g_cnt[NODESN];
__device__ int   g_rowptr[NODESN + 1];
__device__ int   g_cursor[NODESN];
__device__ int   g_epos[EDGESN];
__device__ int   g_bsum[64];

// ---------------- CG init (values computed in fp64 on device) ----------------
__device__ double dfact(int n) {
    const double f[9] = {1.,1.,2.,6.,24.,120.,720.,5040.,40320.};
    return f[n];
}
__device__ double dclebsch(int j1,int m1,int j2,int m2,int j3,int m3) {
    if (m1 + m2 != m3) return 0.0;
    double pref = sqrt((2.0*j3+1.0)*dfact(j3+j1-j2)*dfact(j3-j1+j2)*dfact(j1+j2-j3)/dfact(j1+j2+j3+1));
    pref *= sqrt(dfact(j3+m3)*dfact(j3-m3)*dfact(j1-m1)*dfact(j1+m1)*dfact(j2-m2)*dfact(j2+m2));
    int lo = max(0, max(j2-j3-m1, j1-j3+m2));
    int hi = min(j1+j2-j3, min(j1-m1, j2+m2));
    double s = 0.0;
    for (int k = lo; k <= hi; k++) {
        double d = dfact(k)*dfact(j1+j2-j3-k)*dfact(j1-m1-k)*dfact(j2+m2-k)*dfact(j3-j2+m1+k)*dfact(j3-j1-m2+k);
        s += ((k & 1) ? -1.0 : 1.0) / d;
    }
    return pref * s;
}
__device__ void u_elem(int l, int row, int col, double* re, double* im) {
    int m = row - l;
    const double s2 = 0.7071067811865476;
    double r = 0.0, ii = 0.0;
    double sgn = (m & 1) ? -1.0 : 1.0;
    if (m > 0) {
        if (col == m + l) r = sgn * s2;
        else if (col == l - m) r = s2;
    } else if (m == 0) {
        if (col == l) r = 1.0;
    } else {
        if (col == m + l) ii = s2;
        else if (col == l - m) ii = -sgn * s2;
    }
    *re = r; *im = ii;
}
__constant__ int c_P[15][3] = {{0,0,0},{0,1,1},{0,2,2},{1,0,1},{1,1,0},{1,1,1},{1,1,2},
                               {1,2,1},{1,2,2},{2,0,2},{2,1,1},{2,1,2},{2,2,0},{2,2,1},{2,2,2}};

__global__ void cg_init_kernel() {
    int p = blockIdx.x;
    int l1 = c_P[p][0], l2 = c_P[p][1], l3 = c_P[p][2];
    int d1 = 2*l1+1, d2 = 2*l2+1, d3 = 2*l3+1;
    int t = threadIdx.x;                 // 0..124
    int a = t / 25, b = (t / 5) % 5, c = t % 5;
    double tre = 0.0, tim = 0.0;
    bool inr = (a < d1 && b < d2 && c < d3);
    if (inr) {
        for (int m = 0; m < d1; m++) {
            double u1r, u1i; u_elem(l1, a, m, &u1r, &u1i); u1i = -u1i;
            if (u1r == 0.0 && u1i == 0.0) continue;
            for (int n = 0; n < d2; n++) {
                double u2r, u2i; u_elem(l2, b, n, &u2r, &u2i); u2i = -u2i;
                if (u2r == 0.0 && u2i == 0.0) continue;
                int m3 = (m - l1) + (n - l2);
                if (m3 < -l3 || m3 > l3) continue;
                int o = m3 + l3;
                double u3r, u3i; u_elem(l3, c, o, &u3r, &u3i);
                if (u3r == 0.0 && u3i == 0.0) continue;
                double cv = dclebsch(l1, m-l1, l2, n-l2, l3, m3);
                if (cv == 0.0) continue;
                double pr = u1r*u2r - u1i*u2i;
                double pi = u1r*u2i + u1i*u2r;
                tre += (pr*u3r - pi*u3i) * cv;
                tim += (pr*u3i + pi*u3r) * cv;
            }
        }
    }
    __shared__ double sre[125], sim[125];
    __shared__ int useim;
    sre[t] = fabs(tre); sim[t] = fabs(tim);
    __syncthreads();
    if (t == 0) {
        double mr = 0.0, mi = 0.0;
        for (int q = 0; q < 125; q++) { mr = fmax(mr, sre[q]); mi = fmax(mi, sim[q]); }
        useim = (mi > mr) ? 1 : 0;
    }
    __syncthreads();
    g_CG[p * 125 + t] = inr ? (float)(useim ? tim : tre) : 0.0f;
}

// compile-time superset of real-CG sparsity (values still from g_CG, so superset is safe)
__host__ __device__ constexpr bool cg_ok(int l1,int l2,int l3,int i,int j,int k){
    int m1=i-l1, m2=j-l2, m3=k-l3;
    int a1=m1<0?-m1:m1, a2=m2<0?-m2:m2, a3=m3<0?-m3:m3;
    int s=a1+a2, d=(a1>a2)?(a1-a2):(a2-a1);
    if (a3!=s && a3!=d) return false;
    int neg=(m1<0)+(m2<0)+(m3<0);
    return ((neg&1)==((l1+l2+l3)&1));
}

// ---------------- CSR build ----------------
__global__ void hist_zero_kernel(int* __restrict__ cnt) {
    int i = blockIdx.x * blockDim.x + threadIdx.x;
    if (i < NODESN) cnt[i] = 0;
}
__global__ void hist_kernel(const int* __restrict__ dst, int* __restrict__ cnt) {
    int e = blockIdx.x * blockDim.x + threadIdx.x;
    if (e < EDGESN) atomicAdd(&cnt[dst[e]], 1);
}
__global__ void scan1_kernel(const int* __restrict__ cnt, int* __restrict__ rowptr,
                             int* __restrict__ bsum) {
    __shared__ int tmp[1024];
    int t = threadIdx.x;
    int i = blockIdx.x * 1024 + t;
    int v = (i < NODESN) ? cnt[i] : 0;
    tmp[t] = v;
    __syncthreads();
    for (int off = 1; off < 1024; off <<= 1) {
        int add = (t >= off) ? tmp[t - off] : 0;
        __syncthreads();
        tmp[t] += add;
        __syncthreads();
    }
    if (i < NODESN) rowptr[i + 1] = tmp[t];
    if (t == 1023) bsum[blockIdx.x] = tmp[1023];
}
__global__ void scan2_kernel(int* __restrict__ bsum, int nb) {
    if (threadIdx.x == 0) {
        int run = 0;
        for (int b = 0; b < nb; b++) { int s = bsum[b]; bsum[b] = run; run += s; }
    }
}
__global__ void scan3_kernel(const int* __restrict__ cnt, int* __restrict__ rowptr,
                             int* __restrict__ cursor, const int* __restrict__ bsum) {
    int i = blockIdx.x * 1024 + threadIdx.x;
    if (i < NODESN) {
        int incl = rowptr[i + 1] + bsum[blockIdx.x];
        rowptr[i + 1] = incl;
        cursor[i] = incl - cnt[i];
    }
    if (i == 0) rowptr[0] = 0;
}
__global__ void scatter_kernel(const int* __restrict__ dst, int* __restrict__ cursor,
                               int* __restrict__ epos) {
    int e = blockIdx.x * blockDim.x + threadIdx.x;
    if (e >= EDGESN) return;
    epos[e] = atomicAdd(&cursor[dst[e]], 1);
}

// ---------------- node init ----------------
__global__ void init_nodes_kernel(const int* __restrict__ x, const float* __restrict__ embed_w,
                                  float* __restrict__ hA) {
    int idx = blockIdx.x * blockDim.x + threadIdx.x;
    if (idx >= NODESN * 72) return;
    int n = idx / 72, pos = idx - n * 72;
    hA[idx] = (pos < 8) ? embed_w[x[n] * 8 + pos] : 0.0f;
}

// ---------------- radial MLP with TF32 tensor-core second GEMM ----------------
// Output layout FRAGMENT-NATIVE: per 128-edge block, per 16x8 tile (mtile, nt):
//   element (r, n=nt*8+nn): lane=(r&7)*4+(nn>>1), reg=(r>>3)*2+(nn&1)
__device__ __forceinline__ float to_tf32(float x) {
    uint32_t u;
    asm("cvt.rna.tf32.f32 %0, %1;" : "=r"(u) : "f"(x));
    return __uint_as_float(u);
}

#define HSTR 136   // 136 mod 32 == 8 -> A-fragment LDS conflict-free

// pack W2 (tf32-rounded) into B-fragment order:
// out[(kc*OD + n)*4 + qc] = { W2[(kc*8+qc)*OD+n], W2[(kc*8+qc+4)*OD+n] }
__global__ void pack_w2_kernel(const float* __restrict__ W2, float2* __restrict__ out, int OD) {
    int idx = blockIdx.x * blockDim.x + threadIdx.x;
    if (idx >= 8 * OD * 4) return;
    int kc = idx / (OD * 4);
    int rem = idx - kc * OD * 4;
    int n = rem >> 2, qc = rem & 3;
    out[idx] = make_float2(to_tf32(W2[(kc * 8 + qc) * OD + n]),
                           to_tf32(W2[(kc * 8 + qc + 4) * OD + n]));
}

// one pass: NT n-tiles starting at ntb; accumulators NT*4 regs
template<int OD, int NT>
__device__ __forceinline__ void mma_pass(const float* hidT, const float2* __restrict__ W2p,
                                         const float* B2s, float* woutb,
                                         int ntb, int m0, int warp, int lane) {
    constexpr int NTall = OD / 8;
    int qr = lane >> 2, qc = lane & 3;
    float c0[NT], c1[NT], c2[NT], c3[NT];
    #pragma unroll
    for (int n = 0; n < NT; n++) { c0[n]=0.f; c1[n]=0.f; c2[n]=0.f; c3[n]=0.f; }
    #pragma unroll
    for (int kc = 0; kc < 8; kc++) {
        int kA = kc * 8 + qc;
        uint32_t a0 = __float_as_uint(hidT[kA * HSTR + m0 + qr]);
        uint32_t a1 = __float_as_uint(hidT[kA * HSTR + m0 + qr + 8]);
        uint32_t a2 = __float_as_uint(hidT[(kA + 4) * HSTR + m0 + qr]);
        uint32_t a3 = __float_as_uint(hidT[(kA + 4) * HSTR + m0 + qr + 8]);
        #pragma unroll
        for (int nt = 0; nt < NT; nt++) {
            float2 bv = __ldg(&W2p[(kc * OD + (ntb + nt) * 8) * 4 + qr * 4 + qc]);
            uint32_t b0 = __float_as_uint(bv.x);
            uint32_t b1 = __float_as_uint(bv.y);
            asm volatile("mma.sync.aligned.m16n8k8.row.col.f32.tf32.tf32.f32 "
                         "{%0,%1,%2,%3}, {%4,%5,%6,%7}, {%8,%9}, {%0,%1,%2,%3};"
                         : "+f"(c0[nt]), "+f"(c1[nt]), "+f"(c2[nt]), "+f"(c3[nt])
                         : "r"(a0), "r"(a1), "r"(a2), "r"(a3), "r"(b0), "r"(b1));
        }
    }
    #pragma unroll
    for (int nt = 0; nt < NT; nt++) {
        int n0 = (ntb + nt) * 8 + qc * 2;
        float4 v = make_float4(c0[nt] + B2s[n0], c1[nt] + B2s[n0 + 1],
                               c2[nt] + B2s[n0], c3[nt] + B2s[n0 + 1]);
        *(float4*)&woutb[(size_t)(warp * NTall + ntb + nt) * 128 + lane * 4] = v;
    }
}

template<int OD>
__global__ void __launch_bounds__(256, 5) radial_tc_kernel(
                                 const float* __restrict__ ev,
                                 const float* __restrict__ W1, const float* __restrict__ B1,
                                 const float2* __restrict__ W2p, const float* __restrict__ B2,
                                 float* __restrict__ Wout) {
    extern __shared__ float sm[];
    float* W1s  = sm;                    // 16*64
    float* B1s  = W1s + 1024;            // 64
    float* B2s  = B1s + 64;              // OD
    float* hidT = B2s + OD;              // [64][HSTR] tf32-rounded
    int t = threadIdx.x;
    int e0 = blockIdx.x * 128;
    for (int i = t; i < 1024;   i += 256) W1s[i] = W1[i];
    for (int i = t; i < 64;     i += 256) B1s[i] = B1[i];
    for (int i = t; i < OD;     i += 256) B2s[i] = B2[i];
    __syncthreads();
    // hidden layer: soft-onehot has at most 2 active bins -> 2 FMAs per hidden unit
    {
        int e = t & 127;
        int hg = t >> 7;
        float x = ev[(e0 + e) * 3], y = ev[(e0 + e) * 3 + 1], z = ev[(e0 + e) * 3 + 2];
        float r = sqrtf(x*x + y*y + z*z + 1e-12f);
        float q = r * (17.0f / 3.0f);           // r/step, step = 3/17
        int ib = (int)floorf(q);
        float f0 = 0.0f, f1 = 0.0f;
        int r0 = 0, r1 = 0;
        {
            int b = ib;
            if (b >= 1 && b <= 16) {
                float d = q - (float)b;
                if (fabsf(d) < 1.0f) { f0 = 8.4335731f * __expf(-2.0f / (1.0f - d * d)); r0 = b - 1; }
            }
            b = ib + 1;
            if (b >= 1 && b <= 16) {
                float d = q - (float)b;
                if (fabsf(d) < 1.0f) { f1 = 8.4335731f * __expf(-2.0f / (1.0f - d * d)); r1 = b - 1; }
            }
        }
        const float* w1r0 = &W1s[r0 * 64];
        const float* w1r1 = &W1s[r1 * 64];
        #pragma unroll
        for (int j = 0; j < 32; j++) {
            int h = hg * 32 + j;
            float acc = B1s[h] + f0 * w1r0[h] + f1 * w1r1[h];
            acc = acc / (1.0f + __expf(-acc));
            hidT[h * HSTR + e] = to_tf32(acc);
        }
    }
    __syncthreads();
    // second GEMM 128 x OD x 64: warp -> 1 m-tile, multiple low-register passes over n
    {
        int warp = t >> 5, lane = t & 31;
        int m0 = warp * 16;
        float* woutb = Wout + (size_t)blockIdx.x * (128 * OD);
        if constexpr (OD == 120) {
            mma_pass<OD, 5>(hidT, W2p, B2s, woutb, 0,  m0, warp, lane);
            mma_pass<OD, 5>(hidT, W2p, B2s, woutb, 5,  m0, warp, lane);
            mma_pass<OD, 5>(hidT, W2p, B2s, woutb, 10, m0, warp, lane);
        } else {
            mma_pass<OD, 2>(hidT, W2p, B2s, woutb, 0, m0, warp, lane);
            mma_pass<OD, 1>(hidT, W2p, B2s, woutb, 2, m0, warp, lane);
        }
    }
}

// ---------------- tp_first: write raw m into CSR slot ----------------
__global__ void tp_first_kernel(const float* __restrict__ h, const int* __restrict__ src,
                                const int* __restrict__ epos, const float* __restrict__ ev,
                                const float* __restrict__ w, float* __restrict__ m) {
    int gid = blockIdx.x * blockDim.x + threadIdx.x;
    int e = gid >> 3, c = gid & 7;
    if (e >= EDGESN) return;
    int s = src[e];
    int pos = epos[e];
    float x = ev[e*3], y = ev[e*3+1], z = ev[e*3+2];
    float r = sqrtf(x*x + y*y + z*z + 1e-12f);
    float inv = 1.0f / r; x *= inv; y *= inv; z *= inv;
    const float c3 = 1.7320508076f, c15 = 3.8729833462f, c5 = 2.2360679775f;
    float sh1[3] = { c3*y, c3*z, c3*x };
    float sh2[5] = { c15*x*y, c15*y*z, 0.5f*c5*(3.0f*z*z-1.0f), c15*x*z, 0.5f*c15*(x*x-y*y) };
    float hs = h[s * 72 + c];
    int eL = e & 127;
    int mtile = eL >> 4, rr = eL & 15;
    int lane = (rr & 7) * 4 + (c >> 1);
    int reg = ((rr >> 3) << 1) + (c & 1);
    const float* wb = &w[(size_t)(e >> 7) * 3072 + (size_t)mtile * 384 + lane * 4 + reg];
    float w0 = wb[0], w1v = wb[128], w2v = wb[256];
    float* mp = &m[(size_t)pos * 72];
    mp[c] = w0 * hs;
    float hv = w1v * hs, ht = w2v * hs;
    #pragma unroll
    for (int i = 0; i < 3; i++) mp[8 + c*3 + i] = hv * sh1[i];
    #pragma unroll
    for (int j = 0; j < 5; j++) mp[32 + c*5 + j] = ht * sh2[j];
}

// ---------------- fused streaming gather + update A ----------------
__global__ void updateA_kernel(const float* __restrict__ m, const int* __restrict__ row_ptr,
                               const float* __restrict__ hin, const float* __restrict__ lin0,
                               float* __restrict__ hout) {
    int node = blockIdx.x * 4 + threadIdx.x / 72;
    int k = threadIdx.x % 72;
    if (node >= NODESN || threadIdx.x >= 288) return;
    int beg = row_ptr[node], end = row_ptr[node + 1];
    float acc = 0.0f;
    #pragma unroll 4
    for (int j = beg; j < end; j++) acc += m[(size_t)j * 72 + k];
    float v = acc * 0.25f;
    if (k < 8) {
        float a2 = 0.0f;
        #pragma unroll
        for (int c = 0; c < 8; c++) a2 += hin[node * 72 + c] * lin0[c * 8 + k];
        v += a2 * 0.35355339059f;
        v = v / (1.0f + __expf(-v));
    }
    hout[node * 72 + k] = v;
}

// ---------------- tp_uuu: sparse CG, in-place in CSR slot ----------------
__global__ void tp_uuu_kernel(const float* __restrict__ h, const int* __restrict__ src,
                              const int* __restrict__ epos, const float* __restrict__ w,
                              float* __restrict__ hb) {
    __shared__ float CGs[15 * 125];
    for (int i = threadIdx.x; i < 1875; i += 256) CGs[i] = g_CG[i];
    __syncthreads();
    int gid = blockIdx.x * 256 + threadIdx.x;
    int e = gid >> 3, c = gid & 7;
    if (e >= EDGESN) return;
    int s = src[e];
    int pos = epos[e];
    const float* hp = &h[s * 72];
    float A0[1], A1[3], A2[5], B0[1], B1[3], B2[5];
    A0[0] = hp[c];
    #pragma unroll
    for (int i = 0; i < 3; i++) A1[i] = hp[8 + c*3 + i];
    #pragma unroll
    for (int j = 0; j < 5; j++) A2[j] = hp[32 + c*5 + j];
    float* bp = &hb[(size_t)pos * 72];
    float b0raw = bp[c];
    B0[0] = b0raw / (1.0f + __expf(-b0raw));   // act() applied on consume
    #pragma unroll
    for (int i = 0; i < 3; i++) B1[i] = bp[8 + c*3 + i];
    #pragma unroll
    for (int j = 0; j < 5; j++) B2[j] = bp[32 + c*5 + j];
    // fragment-native w read
    float wp[15];
    {
        int eL = e & 127;
        int mtile = eL >> 4, rr = eL & 15;
        int lane = (rr & 7) * 4 + (c >> 1);
        int reg = ((rr >> 3) << 1) + (c & 1);
        const float* wb = &w[(size_t)(e >> 7) * 15360 + (size_t)mtile * 1920 + lane * 4 + reg];
        #pragma unroll
        for (int p = 0; p < 15; p++) wp[p] = wb[p * 128];
    }
    float O0[1] = {0.f}, O1[3] = {0.f,0.f,0.f}, O2[5] = {0.f,0.f,0.f,0.f,0.f};

#define DOPATH(P, L1, L2, L3, AR, BR, OR, D1, D2, D3) { \
    const float* cg = &CGs[(P) * 125]; float wl = wp[P]; \
    _Pragma("unroll") for (int i = 0; i < (D1); i++) { float aw = AR[i] * wl; \
        _Pragma("unroll") for (int j = 0; j < (D2); j++) { float ab = aw * BR[j]; \
            _Pragma("unroll") for (int k = 0; k < (D3); k++) { \
                if (cg_ok(L1,L2,L3,i,j,k)) OR[k] += ab * cg[i*25 + j*5 + k]; } } } }

    DOPATH(0,  0,0,0, A0, B0, O0, 1, 1, 1)
    DOPATH(1,  0,1,1, A0, B1, O1, 1, 3, 3)
    DOPATH(2,  0,2,2, A0, B2, O2, 1, 5, 5)
    DOPATH(3,  1,0,1, A1, B0, O1, 3, 1, 3)
    DOPATH(4,  1,1,0, A1, B1, O0, 3, 3, 1)
    DOPATH(5,  1,1,1, A1, B1, O1, 3, 3, 3)
    DOPATH(6,  1,1,2, A1, B1, O2, 3, 3, 5)
    DOPATH(7,  1,2,1, A1, B2, O1, 3, 5, 3)
    DOPATH(8,  1,2,2, A1, B2, O2, 3, 5, 5)
    DOPATH(9,  2,0,2, A2, B0, O2, 5, 1, 5)
    DOPATH(10, 2,1,1, A2, B1, O1, 5, 3, 3)
    DOPATH(11, 2,1,2, A2, B1, O2, 5, 3, 5)
    DOPATH(12, 2,2,0, A2, B2, O0, 5, 5, 1)
    DOPATH(13, 2,2,1, A2, B2, O1, 5, 5, 3)
    DOPATH(14, 2,2,2, A2, B2, O2, 5, 5, 5)
#undef DOPATH

    const float n0 = 0.57735026919f, n12 = 0.40824829046f;
    bp[c] = O0[0] * n0;
    #pragma unroll
    for (int i = 0; i < 3; i++) bp[8 + c*3 + i] = O1[i] * n12;
    #pragma unroll
    for (int j = 0; j < 5; j++) bp[32 + c*5 + j] = O2[j] * n12;
}

// ---------------- fused streaming gather + update B ----------------
__global__ void updateB_kernel(const float* __restrict__ m, const int* __restrict__ row_ptr,
                               const float* __restrict__ hin, const float* __restrict__ lin,
                               float* __restrict__ hout) {
    int node = blockIdx.x * 4 + threadIdx.x / 72;
    int k = threadIdx.x % 72;
    if (node >= NODESN || threadIdx.x >= 288) return;
    int beg = row_ptr[node], end = row_ptr[node + 1];
    float acc = 0.0f;
    #pragma unroll 4
    for (int j = beg; j < end; j++) acc += m[(size_t)j * 72 + k];
    float v = acc * 0.25f;
    const float* hp = &hin[node * 72];
    const float R8 = 0.35355339059f;
    float a2 = 0.0f;
    if (k < 8) {
        #pragma unroll
        for (int c = 0; c < 8; c++) a2 += hp[c] * lin[c * 8 + k];
        v += a2 * R8;
        v = v / (1.0f + __expf(-v));
    } else if (k < 32) {
        int dd = (k - 8) / 3, i = (k - 8) % 3;
        #pragma unroll
        for (int c = 0; c < 8; c++) a2 += hp[8 + c*3 + i] * lin[64 + c * 8 + dd];
        v += a2 * R8;
    } else {
        int dd = (k - 32) / 5, j2 = (k - 32) % 5;
        #pragma unroll
        for (int c = 0; c < 8; c++) a2 += hp[32 + c*5 + j2] * lin[128 + c * 8 + dd];
        v += a2 * R8;
    }
    hout[node * 72 + k] = v;
}

// ---------------- readout ----------------
__global__ void readout_kernel(const float* __restrict__ h, const float* __restrict__ ow,
                               float* __restrict__ out) {
    __shared__ float W[1536];
    for (int i = threadIdx.x; i < 1536; i += 256) W[i] = ow[i];
    __syncthreads();
    int n = blockIdx.x * blockDim.x + threadIdx.x;
    if (n >= NODESN) return;
    const float* hp = &h[n * 72];
    float hs[72];
    #pragma unroll
    for (int i = 0; i < 72; i++) hs[i] = hp[i];
    float acc[8] = {0,0,0,0,0,0,0,0};
    const float i1n = 0.57735026919f, i2n = 0.44721359550f;
    #pragma unroll
    for (int i = 0; i < 8; i++) {
        #pragma unroll
        for (int j = 0; j < 8; j++) {
            float p0 = hs[i] * hs[j];
            float p1 = (hs[8+i*3]*hs[8+j*3] + hs[9+i*3]*hs[9+j*3] + hs[10+i*3]*hs[10+j*3]) * i1n;
            float p2 = 0.0f;
            #pragma unroll
            for (int q = 0; q < 5; q++) p2 += hs[32+i*5+q] * hs[32+j*5+q];
            p2 *= i2n;
            int base = (i * 8 + j) * 8;
            #pragma unroll
            for (int k = 0; k < 8; k++)
                acc[k] += p0 * W[base + k] + p1 * W[512 + base + k] + p2 * W[1024 + base + k];
        }
    }
    const float fn = 0.07216878365f;  // 1/sqrt(192)
    #pragma unroll
    for (int k = 0; k < 8; k++) out[n * 8 + k] = acc[k] * fn;
}

// ---------------- launch ----------------
extern "C" void kernel_launch(void* const* d_in, const int* in_sizes, int n_in,
                              void* d_out, int out_size) {
    const int*   x       = (const int*)d_in[0];
    const int*   ei      = (const int*)d_in[1];
    const float* ev      = (const float*)d_in[2];
    const float* embed_w = (const float*)d_in[3];
    const float* lin0    = (const float*)d_in[4];
    const float* lin1    = (const float*)d_in[5];
    const float* lin2    = (const float*)d_in[6];
    const float* out_w   = (const float*)d_in[7];
    const float* r0w1 = (const float*)d_in[8],  *r0b1 = (const float*)d_in[9];
    const float* r0w2 = (const float*)d_in[10], *r0b2 = (const float*)d_in[11];
    const float* r1w1 = (const float*)d_in[12], *r1b1 = (const float*)d_in[13];
    const float* r1w2 = (const float*)d_in[14], *r1b2 = (const float*)d_in[15];
    const float* r2w1 = (const float*)d_in[16], *r2b1 = (const float*)d_in[17];
    const float* r2w2 = (const float*)d_in[18], *r2b2 = (const float*)d_in[19];
    float* out = (float*)d_out;
    const int* src = ei;
    const int* dst = ei + EDGESN;

    float *hA, *hB, *hb, *w0, *w1, *w2;
    float2 *w2p0, *w2p1, *w2p2;
    int *cnt, *rowptr, *cursor, *epos, *bsum;
    cudaGetSymbolAddress((void**)&hA, g_hA);
    cudaGetSymbolAddress((void**)&hB, g_hB);
    cudaGetSymbolAddress((void**)&hb, g_hb);
    cudaGetSymbolAddress((void**)&w0, g_w0);
    cudaGetSymbolAddress((void**)&w1, g_w1);
    cudaGetSymbolAddress((void**)&w2, g_w2);
    cudaGetSymbolAddress((void**)&w2p0, g_w2p0);
    cudaGetSymbolAddress((void**)&w2p1, g_w2p1);
    cudaGetSymbolAddress((void**)&w2p2, g_w2p2);
    cudaGetSymbolAddress((void**)&cnt, g_cnt);
    cudaGetSymbolAddress((void**)&rowptr, g_rowptr);
    cudaGetSymbolAddress((void**)&cursor, g_cursor);
    cudaGetSymbolAddress((void**)&epos, g_epos);
    cudaGetSymbolAddress((void**)&bsum, g_bsum);

    size_t sh24  = (size_t)(1024 + 64 + 24 + 64*HSTR) * 4;    // 39264 B
    size_t sh120 = (size_t)(1024 + 64 + 120 + 64*HSTR) * 4;   // 39648 B
    cudaFuncSetAttribute(radial_tc_kernel<24>,  cudaFuncAttributeMaxDynamicSharedMemorySize, (int)sh24);
    cudaFuncSetAttribute(radial_tc_kernel<120>, cudaFuncAttributeMaxDynamicSharedMemorySize, (int)sh120);

    const int NB72 = (NODESN * 72 + 255) / 256;
    const int NGB  = (NODESN + 3) / 4;
    const int NSCAN = (NODESN + 1023) / 1024;     // 40

    cg_init_kernel<<<15, 125>>>();
    hist_zero_kernel<<<(NODESN + 255) / 256, 256>>>(cnt);
    pack_w2_kernel<<<(8 * 120 * 4 + 255) / 256, 256>>>(r2w2, w2p2, 120);
    // 4th launch = profiled slot
    radial_tc_kernel<120><<<EDGESN / 128, 256, sh120>>>(ev, r2w1, r2b1, w2p2, r2b2, w2);
    hist_kernel<<<(EDGESN + 255) / 256, 256>>>(dst, cnt);
    scan1_kernel<<<NSCAN, 1024>>>(cnt, rowptr, bsum);
    scan2_kernel<<<1, 32>>>(bsum, NSCAN);
    scan3_kernel<<<NSCAN, 1024>>>(cnt, rowptr, cursor, bsum);
    scatter_kernel<<<(EDGESN + 255) / 256, 256>>>(dst, cursor, epos);
    pack_w2_kernel<<<(8 * 24 * 4 + 255) / 256, 256>>>(r0w2, w2p0, 24);
    pack_w2_kernel<<<(8 * 120 * 4 + 255) / 256, 256>>>(r1w2, w2p1, 120);

    init_nodes_kernel<<<NB72, 256>>>(x, embed_w, hA);

    radial_tc_kernel<24><<<EDGESN / 128, 256, sh24>>>(ev, r0w1, r0b1, w2p0, r0b2, w0);
    tp_first_kernel<<<EDGESN * 8 / 256, 256>>>(hA, src, epos, ev, w0, hb);
    updateA_kernel<<<NGB, 288>>>(hb, rowptr, hA, lin0, hB);

    radial_tc_kernel<120><<<EDGESN / 128, 256, sh120>>>(ev, r1w1, r1b1, w2p1, r1b2, w1);
    tp_uuu_kernel<<<EDGESN * 8 / 256, 256>>>(hB, src, epos, w1, hb);
    updateB_kernel<<<NGB, 288>>>(hb, rowptr, hB, lin1, hA);

    tp_uuu_kernel<<<EDGESN * 8 / 256, 256>>>(hA, src, epos, w2, hb);
    updateB_kernel<<<NGB, 288>>>(hb, rowptr, hA, lin2, hB);

    readout_kernel<<<(NODESN + 255) / 256, 256>>>(hB, out_w, out);
}

// round 14
// speedup vs baseline: 1.0173x; 1.0173x over previous
#include <cuda_runtime.h>
#include <cuda_bf16.h>
#include <math.h>
#include <stdint.h>

#define NODESN 40000
#define EDGESN 640000

// ---------------- static device scratch ----------------
__device__ float g_CG[15 * 125];
__device__ float g_hA[NODESN * 72];
__device__ float g_hB[NODESN * 72];
__device__ float g_hb[EDGESN * 72];     // messages, stored in CSR slot order
__device__ float g_w0[EDGESN * 24];
__device__ float g_w1[EDGESN * 120];
__device__ float g_w2[EDGESN * 120];
__device__ float4 g_w4p0[4 * 24 * 4];   // packed tf32 W2 (k-paired), layer0
__device__ float4 g_w4p1[4 * 120 * 4];  // layer1
__device__ float4 g_w4p2[4 * 120 * 4];  // layer2
__device__ int   g_cnt[NODESN];
__device__ int   g_rowptr[NODESN + 1];
__device__ int   g_cursor[NODESN];
__device__ int   g_epos[EDGESN];
__device__ int   g_bsum[64];

// ---------------- CG init (values computed in fp64 on device) ----------------
__device__ double dfact(int n) {
    const double f[9] = {1.,1.,2.,6.,24.,120.,720.,5040.,40320.};
    return f[n];
}
__device__ double dclebsch(int j1,int m1,int j2,int m2,int j3,int m3) {
    if (m1 + m2 != m3) return 0.0;
    double pref = sqrt((2.0*j3+1.0)*dfact(j3+j1-j2)*dfact(j3-j1+j2)*dfact(j1+j2-j3)/dfact(j1+j2+j3+1));
    pref *= sqrt(dfact(j3+m3)*dfact(j3-m3)*dfact(j1-m1)*dfact(j1+m1)*dfact(j2-m2)*dfact(j2+m2));
    int lo = max(0, max(j2-j3-m1, j1-j3+m2));
    int hi = min(j1+j2-j3, min(j1-m1, j2+m2));
    double s = 0.0;
    for (int k = lo; k <= hi; k++) {
        double d = dfact(k)*dfact(j1+j2-j3-k)*dfact(j1-m1-k)*dfact(j2+m2-k)*dfact(j3-j2+m1+k)*dfact(j3-j1-m2+k);
        s += ((k & 1) ? -1.0 : 1.0) / d;
    }
    return pref * s;
}
__device__ void u_elem(int l, int row, int col, double* re, double* im) {
    int m = row - l;
    const double s2 = 0.7071067811865476;
    double r = 0.0, ii = 0.0;
    double sgn = (m & 1) ? -1.0 : 1.0;
    if (m > 0) {
        if (col == m + l) r = sgn * s2;
        else if (col == l - m) r = s2;
    } else if (m == 0) {
        if (col == l) r = 1.0;
    } else {
        if (col == m + l) ii = s2;
        else if (col == l - m) ii = -sgn * s2;
    }
    *re = r; *im = ii;
}
__constant__ int c_P[15][3] = {{0,0,0},{0,1,1},{0,2,2},{1,0,1},{1,1,0},{1,1,1},{1,1,2},
                               {1,2,1},{1,2,2},{2,0,2},{2,1,1},{2,1,2},{2,2,0},{2,2,1},{2,2,2}};

__global__ void cg_init_kernel() {
    int p = blockIdx.x;
    int l1 = c_P[p][0], l2 = c_P[p][1], l3 = c_P[p][2];
    int d1 = 2*l1+1, d2 = 2*l2+1, d3 = 2*l3+1;
    int t = threadIdx.x;                 // 0..124
    int a = t / 25, b = (t / 5) % 5, c = t % 5;
    double tre = 0.0, tim = 0.0;
    bool inr = (a < d1 && b < d2 && c < d3);
    if (inr) {
        for (int m = 0; m < d1; m++) {
            double u1r, u1i; u_elem(l1, a, m, &u1r, &u1i); u1i = -u1i;
            if (u1r == 0.0 && u1i == 0.0) continue;
            for (int n = 0; n < d2; n++) {
                double u2r, u2i; u_elem(l2, b, n, &u2r, &u2i); u2i = -u2i;
                if (u2r == 0.0 && u2i == 0.0) continue;
                int m3 = (m - l1) + (n - l2);
                if (m3 < -l3 || m3 > l3) continue;
                int o = m3 + l3;
                double u3r, u3i; u_elem(l3, c, o, &u3r, &u3i);
                if (u3r == 0.0 && u3i == 0.0) continue;
                double cv = dclebsch(l1, m-l1, l2, n-l2, l3, m3);
                if (cv == 0.0) continue;
                double pr = u1r*u2r - u1i*u2i;
                double pi = u1r*u2i + u1i*u2r;
                tre += (pr*u3r - pi*u3i) * cv;
                tim += (pr*u3i + pi*u3r) * cv;
            }
        }
    }
    __shared__ double sre[125], sim[125];
    __shared__ int useim;
    sre[t] = fabs(tre); sim[t] = fabs(tim);
    __syncthreads();
    if (t == 0) {
        double mr = 0.0, mi = 0.0;
        for (int q = 0; q < 125; q++) { mr = fmax(mr, sre[q]); mi = fmax(mi, sim[q]); }
        useim = (mi > mr) ? 1 : 0;
    }
    __syncthreads();
    g_CG[p * 125 + t] = inr ? (float)(useim ? tim : tre) : 0.0f;
}

// compile-time superset of real-CG sparsity (values still from g_CG, so superset is safe)
__host__ __device__ constexpr bool cg_ok(int l1,int l2,int l3,int i,int j,int k){
    int m1=i-l1, m2=j-l2, m3=k-l3;
    int a1=m1<0?-m1:m1, a2=m2<0?-m2:m2, a3=m3<0?-m3:m3;
    int s=a1+a2, d=(a1>a2)?(a1-a2):(a2-a1);
    if (a3!=s && a3!=d) return false;
    int neg=(m1<0)+(m2<0)+(m3<0);
    return ((neg&1)==((l1+l2+l3)&1));
}

// ---------------- CSR build ----------------
__global__ void hist_zero_kernel(int* __restrict__ cnt) {
    int i = blockIdx.x * blockDim.x + threadIdx.x;
    if (i < NODESN) cnt[i] = 0;
}
__global__ void hist_kernel(const int* __restrict__ dst, int* __restrict__ cnt) {
    int e = blockIdx.x * blockDim.x + threadIdx.x;
    if (e < EDGESN) atomicAdd(&cnt[dst[e]], 1);
}
__global__ void scan1_kernel(const int* __restrict__ cnt, int* __restrict__ rowptr,
                             int* __restrict__ bsum) {
    __shared__ int tmp[1024];
    int t = threadIdx.x;
    int i = blockIdx.x * 1024 + t;
    int v = (i < NODESN) ? cnt[i] : 0;
    tmp[t] = v;
    __syncthreads();
    for (int off = 1; off < 1024; off <<= 1) {
        int add = (t >= off) ? tmp[t - off] : 0;
        __syncthreads();
        tmp[t] += add;
        __syncthreads();
    }
    if (i < NODESN) rowptr[i + 1] = tmp[t];
    if (t == 1023) bsum[blockIdx.x] = tmp[1023];
}
__global__ void scan2_kernel(int* __restrict__ bsum, int nb) {
    if (threadIdx.x == 0) {
        int run = 0;
        for (int b = 0; b < nb; b++) { int s = bsum[b]; bsum[b] = run; run += s; }
    }
}
__global__ void scan3_kernel(const int* __restrict__ cnt, int* __restrict__ rowptr,
                             int* __restrict__ cursor, const int* __restrict__ bsum) {
    int i = blockIdx.x * 1024 + threadIdx.x;
    if (i < NODESN) {
        int incl = rowptr[i + 1] + bsum[blockIdx.x];
        rowptr[i + 1] = incl;
        cursor[i] = incl - cnt[i];
    }
    if (i == 0) rowptr[0] = 0;
}
__global__ void scatter_kernel(const int* __restrict__ dst, int* __restrict__ cursor,
                               int* __restrict__ epos) {
    int e = blockIdx.x * blockDim.x + threadIdx.x;
    if (e >= EDGESN) return;
    epos[e] = atomicAdd(&cursor[dst[e]], 1);
}

// ---------------- node init ----------------
__global__ void init_nodes_kernel(const int* __restrict__ x, const float* __restrict__ embed_w,
                                  float* __restrict__ hA) {
    int idx = blockIdx.x * blockDim.x + threadIdx.x;
    if (idx >= NODESN * 72) return;
    int n = idx / 72, pos = idx - n * 72;
    hA[idx] = (pos < 8) ? embed_w[x[n] * 8 + pos] : 0.0f;
}

// ---------------- radial MLP with TF32 tensor-core second GEMM ----------------
// Output layout FRAGMENT-NATIVE: per 128-edge block, per 16x8 tile (mtile, nt):
//   element (r, n=nt*8+nn): lane=(r&7)*4+(nn>>1), reg=(r>>3)*2+(nn&1)
__device__ __forceinline__ float to_tf32(float x) {
    uint32_t u;
    asm("cvt.rna.tf32.f32 %0, %1;" : "=r"(u) : "f"(x));
    return __uint_as_float(u);
}

#define HSTR 136   // 136 mod 32 == 8 -> A-fragment LDS conflict-free

// pack W2 (tf32-rounded) into k-paired B-fragment order:
// out[(kc2*OD + n)*4 + qc] = { W2[(kc2*16+qc)*OD+n],    W2[(kc2*16+qc+4)*OD+n],
//                              W2[(kc2*16+qc+8)*OD+n],  W2[(kc2*16+qc+12)*OD+n] }
// In-kernel index: (kc2*OD + nbase)*4 + (qr*4+qc) == ...*4 + lane  (since n = nbase + qr)
__global__ void pack_w2_kernel(const float* __restrict__ W2, float4* __restrict__ out, int OD) {
    int idx = blockIdx.x * blockDim.x + threadIdx.x;
    if (idx >= 4 * OD * 4) return;
    int kc2 = idx / (OD * 4);
    int rem = idx - kc2 * OD * 4;
    int n = rem >> 2, qc = rem & 3;
    out[idx] = make_float4(to_tf32(W2[(kc2 * 16 + qc) * OD + n]),
                           to_tf32(W2[(kc2 * 16 + qc + 4) * OD + n]),
                           to_tf32(W2[(kc2 * 16 + qc + 8) * OD + n]),
                           to_tf32(W2[(kc2 * 16 + qc + 12) * OD + n]));
}

// one pass: NT n-tiles starting at ntb; accumulators NT*4 regs; k covered in 4 pairs
template<int OD, int NT>
__device__ __forceinline__ void mma_pass(const float* hidT, const float4* __restrict__ W4p,
                                         const float* B2s, float* woutb,
                                         int ntb, int m0, int warp, int lane) {
    constexpr int NTall = OD / 8;
    int qr = lane >> 2, qc = lane & 3;
    float c0[NT], c1[NT], c2[NT], c3[NT];
    #pragma unroll
    for (int n = 0; n < NT; n++) { c0[n]=0.f; c1[n]=0.f; c2[n]=0.f; c3[n]=0.f; }
    #pragma unroll
    for (int kc2 = 0; kc2 < 4; kc2++) {
        int kA  = kc2 * 16 + qc;
        int kA2 = kA + 8;
        uint32_t a0 = __float_as_uint(hidT[kA * HSTR + m0 + qr]);
        uint32_t a1 = __float_as_uint(hidT[kA * HSTR + m0 + qr + 8]);
        uint32_t a2 = __float_as_uint(hidT[(kA + 4) * HSTR + m0 + qr]);
        uint32_t a3 = __float_as_uint(hidT[(kA + 4) * HSTR + m0 + qr + 8]);
        uint32_t a4 = __float_as_uint(hidT[kA2 * HSTR + m0 + qr]);
        uint32_t a5 = __float_as_uint(hidT[kA2 * HSTR + m0 + qr + 8]);
        uint32_t a6 = __float_as_uint(hidT[(kA2 + 4) * HSTR + m0 + qr]);
        uint32_t a7 = __float_as_uint(hidT[(kA2 + 4) * HSTR + m0 + qr + 8]);
        #pragma unroll
        for (int nt = 0; nt < NT; nt++) {
            float4 bv = __ldg(&W4p[(kc2 * OD + (ntb + nt) * 8) * 4 + lane]);
            uint32_t b0 = __float_as_uint(bv.x);
            uint32_t b1 = __float_as_uint(bv.y);
            uint32_t b2 = __float_as_uint(bv.z);
            uint32_t b3 = __float_as_uint(bv.w);
            asm volatile("mma.sync.aligned.m16n8k8.row.col.f32.tf32.tf32.f32 "
                         "{%0,%1,%2,%3}, {%4,%5,%6,%7}, {%8,%9}, {%0,%1,%2,%3};"
                         : "+f"(c0[nt]), "+f"(c1[nt]), "+f"(c2[nt]), "+f"(c3[nt])
                         : "r"(a0), "r"(a1), "r"(a2), "r"(a3), "r"(b0), "r"(b1));
            asm volatile("mma.sync.aligned.m16n8k8.row.col.f32.tf32.tf32.f32 "
                         "{%0,%1,%2,%3}, {%4,%5,%6,%7}, {%8,%9}, {%0,%1,%2,%3};"
                         : "+f"(c0[nt]), "+f"(c1[nt]), "+f"(c2[nt]), "+f"(c3[nt])
                         : "r"(a4), "r"(a5), "r"(a6), "r"(a7), "r"(b2), "r"(b3));
        }
    }
    #pragma unroll
    for (int nt = 0; nt < NT; nt++) {
        int n0 = (ntb + nt) * 8 + qc * 2;
        float4 v = make_float4(c0[nt] + B2s[n0], c1[nt] + B2s[n0 + 1],
                               c2[nt] + B2s[n0], c3[nt] + B2s[n0 + 1]);
        *(float4*)&woutb[(size_t)(warp * NTall + ntb + nt) * 128 + lane * 4] = v;
    }
}

template<int OD>
__global__ void __launch_bounds__(256, 4) radial_tc_kernel(
                                 const float* __restrict__ ev,
                                 const float* __restrict__ W1, const float* __restrict__ B1,
                                 const float4* __restrict__ W4p, const float* __restrict__ B2,
                                 float* __restrict__ Wout) {
    extern __shared__ float sm[];
    float* W1s  = sm;                    // 16*64
    float* B1s  = W1s + 1024;            // 64
    float* B2s  = B1s + 64;              // OD
    float* hidT = B2s + OD;              // [64][HSTR] tf32-rounded
    int t = threadIdx.x;
    int e0 = blockIdx.x * 128;
    for (int i = t; i < 1024;   i += 256) W1s[i] = W1[i];
    for (int i = t; i < 64;     i += 256) B1s[i] = B1[i];
    for (int i = t; i < OD;     i += 256) B2s[i] = B2[i];
    __syncthreads();
    // hidden layer: soft-onehot has at most 2 active bins -> 2 FMAs per hidden unit
    {
        int e = t & 127;
        int hg = t >> 7;
        float x = ev[(e0 + e) * 3], y = ev[(e0 + e) * 3 + 1], z = ev[(e0 + e) * 3 + 2];
        float r = sqrtf(x*x + y*y + z*z + 1e-12f);
        float q = r * (17.0f / 3.0f);           // r/step, step = 3/17
        int ib = (int)floorf(q);
        float f0 = 0.0f, f1 = 0.0f;
        int r0 = 0, r1 = 0;
        {
            int b = ib;
            if (b >= 1 && b <= 16) {
                float d = q - (float)b;
                if (fabsf(d) < 1.0f) { f0 = 8.4335731f * __expf(-2.0f / (1.0f - d * d)); r0 = b - 1; }
            }
            b = ib + 1;
            if (b >= 1 && b <= 16) {
                float d = q - (float)b;
                if (fabsf(d) < 1.0f) { f1 = 8.4335731f * __expf(-2.0f / (1.0f - d * d)); r1 = b - 1; }
            }
        }
        const float* w1r0 = &W1s[r0 * 64];
        const float* w1r1 = &W1s[r1 * 64];
        #pragma unroll
        for (int j = 0; j < 32; j++) {
            int h = hg * 32 + j;
            float acc = B1s[h] + f0 * w1r0[h] + f1 * w1r1[h];
            acc = acc / (1.0f + __expf(-acc));
            hidT[h * HSTR + e] = to_tf32(acc);
        }
    }
    __syncthreads();
    // second GEMM 128 x OD x 64: warp -> 1 m-tile, two accumulator passes over n
    {
        constexpr int NTT = OD / 8;
        constexpr int NT0 = (NTT + 1) / 2;
        constexpr int NT1 = NTT - NT0;
        int warp = t >> 5, lane = t & 31;
        int m0 = warp * 16;
        float* woutb = Wout + (size_t)blockIdx.x * (128 * OD);
        mma_pass<OD, NT0>(hidT, W4p, B2s, woutb, 0,   m0, warp, lane);
        if (NT1 > 0)
            mma_pass<OD, NT1>(hidT, W4p, B2s, woutb, NT0, m0, warp, lane);
    }
}

// ---------------- tp_first: write raw m into CSR slot ----------------
__global__ void tp_first_kernel(const float* __restrict__ h, const int* __restrict__ src,
                                const int* __restrict__ epos, const float* __restrict__ ev,
                                const float* __restrict__ w, float* __restrict__ m) {
    int gid = blockIdx.x * blockDim.x + threadIdx.x;
    int e = gid >> 3, c = gid & 7;
    if (e >= EDGESN) return;
    int s = src[e];
    int pos = epos[e];
    float x = ev[e*3], y = ev[e*3+1], z = ev[e*3+2];
    float r = sqrtf(x*x + y*y + z*z + 1e-12f);
    float inv = 1.0f / r; x *= inv; y *= inv; z *= inv;
    const float c3 = 1.7320508076f, c15 = 3.8729833462f, c5 = 2.2360679775f;
    float sh1[3] = { c3*y, c3*z, c3*x };
    float sh2[5] = { c15*x*y, c15*y*z, 0.5f*c5*(3.0f*z*z-1.0f), c15*x*z, 0.5f*c15*(x*x-y*y) };
    float hs = h[s * 72 + c];
    int eL = e & 127;
    int mtile = eL >> 4, rr = eL & 15;
    int lane = (rr & 7) * 4 + (c >> 1);
    int reg = ((rr >> 3) << 1) + (c & 1);
    const float* wb = &w[(size_t)(e >> 7) * 3072 + (size_t)mtile * 384 + lane * 4 + reg];
    float w0 = wb[0], w1v = wb[128], w2v = wb[256];
    float* mp = &m[(size_t)pos * 72];
    mp[c] = w0 * hs;
    float hv = w1v * hs, ht = w2v * hs;
    #pragma unroll
    for (int i = 0; i < 3; i++) mp[8 + c*3 + i] = hv * sh1[i];
    #pragma unroll
    for (int j = 0; j < 5; j++) mp[32 + c*5 + j] = ht * sh2[j];
}

// ---------------- fused streaming gather + update A ----------------
__global__ void updateA_kernel(const float* __restrict__ m, const int* __restrict__ row_ptr,
                               const float* __restrict__ hin, const float* __restrict__ lin0,
                               float* __restrict__ hout) {
    int node = blockIdx.x * 4 + threadIdx.x / 72;
    int k = threadIdx.x % 72;
    if (node >= NODESN || threadIdx.x >= 288) return;
    int beg = row_ptr[node], end = row_ptr[node + 1];
    float acc = 0.0f;
    #pragma unroll 4
    for (int j = beg; j < end; j++) acc += m[(size_t)j * 72 + k];
    float v = acc * 0.25f;
    if (k < 8) {
        float a2 = 0.0f;
        #pragma unroll
        for (int c = 0; c < 8; c++) a2 += hin[node * 72 + c] * lin0[c * 8 + k];
        v += a2 * 0.35355339059f;
        v = v / (1.0f + __expf(-v));
    }
    hout[node * 72 + k] = v;
}

// ---------------- tp_uuu: sparse CG, in-place in CSR slot ----------------
__global__ void tp_uuu_kernel(const float* __restrict__ h, const int* __restrict__ src,
                              const int* __restrict__ epos, const float* __restrict__ w,
                              float* __restrict__ hb) {
    __shared__ float CGs[15 * 125];
    for (int i = threadIdx.x; i < 1875; i += 256) CGs[i] = g_CG[i];
    __syncthreads();
    int gid = blockIdx.x * 256 + threadIdx.x;
    int e = gid >> 3, c = gid & 7;
    if (e >= EDGESN) return;
    int s = src[e];
    int pos = epos[e];
    const float* hp = &h[s * 72];
    float A0[1], A1[3], A2[5], B0[1], B1[3], B2[5];
    A0[0] = hp[c];
    #pragma unroll
    for (int i = 0; i < 3; i++) A1[i] = hp[8 + c*3 + i];
    #pragma unroll
    for (int j = 0; j < 5; j++) A2[j] = hp[32 + c*5 + j];
    float* bp = &hb[(size_t)pos * 72];
    float b0raw = bp[c];
    B0[0] = b0raw / (1.0f + __expf(-b0raw));   // act() applied on consume
    #pragma unroll
    for (int i = 0; i < 3; i++) B1[i] = bp[8 + c*3 + i];
    #pragma unroll
    for (int j = 0; j < 5; j++) B2[j] = bp[32 + c*5 + j];
    // fragment-native w read
    float wp[15];
    {
        int eL = e & 127;
        int mtile = eL >> 4, rr = eL & 15;
        int lane = (rr & 7) * 4 + (c >> 1);
        int reg = ((rr >> 3) << 1) + (c & 1);
        const float* wb = &w[(size_t)(e >> 7) * 15360 + (size_t)mtile * 1920 + lane * 4 + reg];
        #pragma unroll
        for (int p = 0; p < 15; p++) wp[p] = wb[p * 128];
    }
    float O0[1] = {0.f}, O1[3] = {0.f,0.f,0.f}, O2[5] = {0.f,0.f,0.f,0.f,0.f};

#define DOPATH(P, L1, L2, L3, AR, BR, OR, D1, D2, D3) { \
    const float* cg = &CGs[(P) * 125]; float wl = wp[P]; \
    _Pragma("unroll") for (int i = 0; i < (D1); i++) { float aw = AR[i] * wl; \
        _Pragma("unroll") for (int j = 0; j < (D2); j++) { float ab = aw * BR[j]; \
            _Pragma("unroll") for (int k = 0; k < (D3); k++) { \
                if (cg_ok(L1,L2,L3,i,j,k)) OR[k] += ab * cg[i*25 + j*5 + k]; } } } }

    DOPATH(0,  0,0,0, A0, B0, O0, 1, 1, 1)
    DOPATH(1,  0,1,1, A0, B1, O1, 1, 3, 3)
    DOPATH(2,  0,2,2, A0, B2, O2, 1, 5, 5)
    DOPATH(3,  1,0,1, A1, B0, O1, 3, 1, 3)
    DOPATH(4,  1,1,0, A1, B1, O0, 3, 3, 1)
    DOPATH(5,  1,1,1, A1, B1, O1, 3, 3, 3)
    DOPATH(6,  1,1,2, A1, B1, O2, 3, 3, 5)
    DOPATH(7,  1,2,1, A1, B2, O1, 3, 5, 3)
    DOPATH(8,  1,2,2, A1, B2, O2, 3, 5, 5)
    DOPATH(9,  2,0,2, A2, B0, O2, 5, 1, 5)
    DOPATH(10, 2,1,1, A2, B1, O1, 5, 3, 3)
    DOPATH(11, 2,1,2, A2, B1, O2, 5, 3, 5)
    DOPATH(12, 2,2,0, A2, B2, O0, 5, 5, 1)
    DOPATH(13, 2,2,1, A2, B2, O1, 5, 5, 3)
    DOPATH(14, 2,2,2, A2, B2, O2, 5, 5, 5)
#undef DOPATH

    const float n0 = 0.57735026919f, n12 = 0.40824829046f;
    bp[c] = O0[0] * n0;
    #pragma unroll
    for (int i = 0; i < 3; i++) bp[8 + c*3 + i] = O1[i] * n12;
    #pragma unroll
    for (int j = 0; j < 5; j++) bp[32 + c*5 + j] = O2[j] * n12;
}

// ---------------- fused streaming gather + update B ----------------
__global__ void updateB_kernel(const float* __restrict__ m, const int* __restrict__ row_ptr,
                               const float* __restrict__ hin, const float* __restrict__ lin,
                               float* __restrict__ hout) {
    int node = blockIdx.x * 4 + threadIdx.x / 72;
    int k = threadIdx.x % 72;
    if (node >= NODESN || threadIdx.x >= 288) return;
    int beg = row_ptr[node], end = row_ptr[node + 1];
    float acc = 0.0f;
    #pragma unroll 4
    for (int j = beg; j < end; j++) acc += m[(size_t)j * 72 + k];
    float v = acc * 0.25f;
    const float* hp = &hin[node * 72];
    const float R8 = 0.35355339059f;
    float a2 = 0.0f;
    if (k < 8) {
        #pragma unroll
        for (int c = 0; c < 8; c++) a2 += hp[c] * lin[c * 8 + k];
        v += a2 * R8;
        v = v / (1.0f + __expf(-v));
    } else if (k < 32) {
        int dd = (k - 8) / 3, i = (k - 8) % 3;
        #pragma unroll
        for (int c = 0; c < 8; c++) a2 += hp[8 + c*3 + i] * lin[64 + c * 8 + dd];
        v += a2 * R8;
    } else {
        int dd = (k - 32) / 5, j2 = (k - 32) % 5;
        #pragma unroll
        for (int c = 0; c < 8; c++) a2 += hp[32 + c*5 + j2] * lin[128 + c * 8 + dd];
        v += a2 * R8;
    }
    hout[node * 72 + k] = v;
}

// ---------------- readout ----------------
__global__ void readout_kernel(const float* __restrict__ h, const float* __restrict__ ow,
                               float* __restrict__ out) {
    __shared__ float W[1536];
    for (int i = threadIdx.x; i < 1536; i += 256) W[i] = ow[i];
    __syncthreads();
    int n = blockIdx.x * blockDim.x + threadIdx.x;
    if (n >= NODESN) return;
    const float* hp = &h[n * 72];
    float hs[72];
    #pragma unroll
    for (int i = 0; i < 72; i++) hs[i] = hp[i];
    float acc[8] = {0,0,0,0,0,0,0,0};
    const float i1n = 0.57735026919f, i2n = 0.44721359550f;
    #pragma unroll
    for (int i = 0; i < 8; i++) {
        #pragma unroll
        for (int j = 0; j < 8; j++) {
            float p0 = hs[i] * hs[j];
            float p1 = (hs[8+i*3]*hs[8+j*3] + hs[9+i*3]*hs[9+j*3] + hs[10+i*3]*hs[10+j*3]) * i1n;
            float p2 = 0.0f;
            #pragma unroll
            for (int q = 0; q < 5; q++) p2 += hs[32+i*5+q] * hs[32+j*5+q];
            p2 *= i2n;
            int base = (i * 8 + j) * 8;
            #pragma unroll
            for (int k = 0; k < 8; k++)
                acc[k] += p0 * W[base + k] + p1 * W[512 + base + k] + p2 * W[1024 + base + k];
        }
    }
    const float fn = 0.07216878365f;  // 1/sqrt(192)
    #pragma unroll
    for (int k = 0; k < 8; k++) out[n * 8 + k] = acc[k] * fn;
}

// ---------------- launch ----------------
extern "C" void kernel_launch(void* const* d_in, const int* in_sizes, int n_in,
                              void* d_out, int out_size) {
    const int*   x       = (const int*)d_in[0];
    const int*   ei      = (const int*)d_in[1];
    const float* ev      = (const float*)d_in[2];
    const float* embed_w = (const float*)d_in[3];
    const float* lin0    = (const float*)d_in[4];
    const float* lin1    = (const float*)d_in[5];
    const float* lin2    = (const float*)d_in[6];
    const float* out_w   = (const float*)d_in[7];
    const float* r0w1 = (const float*)d_in[8],  *r0b1 = (const float*)d_in[9];
    const float* r0w2 = (const float*)d_in[10], *r0b2 = (const float*)d_in[11];
    const float* r1w1 = (const float*)d_in[12], *r1b1 = (const float*)d_in[13];
    const float* r1w2 = (const float*)d_in[14], *r1b2 = (const float*)d_in[15];
    const float* r2w1 = (const float*)d_in[16], *r2b1 = (const float*)d_in[17];
    const float* r2w2 = (const float*)d_in[18], *r2b2 = (const float*)d_in[19];
    float* out = (float*)d_out;
    const int* src = ei;
    const int* dst = ei + EDGESN;

    float *hA, *hB, *hb, *w0, *w1, *w2;
    float4 *w4p0, *w4p1, *w4p2;
    int *cnt, *rowptr, *cursor, *epos, *bsum;
    cudaGetSymbolAddress((void**)&hA, g_hA);
    cudaGetSymbolAddress((void**)&hB, g_hB);
    cudaGetSymbolAddress((void**)&hb, g_hb);
    cudaGetSymbolAddress((void**)&w0, g_w0);
    cudaGetSymbolAddress((void**)&w1, g_w1);
    cudaGetSymbolAddress((void**)&w2, g_w2);
    cudaGetSymbolAddress((void**)&w4p0, g_w4p0);
    cudaGetSymbolAddress((void**)&w4p1, g_w4p1);
    cudaGetSymbolAddress((void**)&w4p2, g_w4p2);
    cudaGetSymbolAddress((void**)&cnt, g_cnt);
    cudaGetSymbolAddress((void**)&rowptr, g_rowptr);
    cudaGetSymbolAddress((void**)&cursor, g_cursor);
    cudaGetSymbolAddress((void**)&epos, g_epos);
    cudaGetSymbolAddress((void**)&bsum, g_bsum);

    size_t sh24  = (size_t)(1024 + 64 + 24 + 64*HSTR) * 4;    // 39264 B
    size_t sh120 = (size_t)(1024 + 64 + 120 + 64*HSTR) * 4;   // 39648 B
    cudaFuncSetAttribute(radial_tc_kernel<24>,  cudaFuncAttributeMaxDynamicSharedMemorySize, (int)sh24);
    cudaFuncSetAttribute(radial_tc_kernel<120>, cudaFuncAttributeMaxDynamicSharedMemorySize, (int)sh120);

    const int NB72 = (NODESN * 72 + 255) / 256;
    const int NGB  = (NODESN + 3) / 4;
    const int NSCAN = (NODESN + 1023) / 1024;     // 40

    cg_init_kernel<<<15, 125>>>();
    hist_zero_kernel<<<(NODESN + 255) / 256, 256>>>(cnt);
    pack_w2_kernel<<<(4 * 120 * 4 + 255) / 256, 256>>>(r2w2, w4p2, 120);
    // 4th launch = profiled slot
    radial_tc_kernel<120><<<EDGESN / 128, 256, sh120>>>(ev, r2w1, r2b1, w4p2, r2b2, w2);
    hist_kernel<<<(EDGESN + 255) / 256, 256>>>(dst, cnt);
    scan1_kernel<<<NSCAN, 1024>>>(cnt, rowptr, bsum);
    scan2_kernel<<<1, 32>>>(bsum, NSCAN);
    scan3_kernel<<<NSCAN, 1024>>>(cnt, rowptr, cursor, bsum);
    scatter_kernel<<<(EDGESN + 255) / 256, 256>>>(dst, cursor, epos);
    pack_w2_kernel<<<(4 * 24 * 4 + 255) / 256, 256>>>(r0w2, w4p0, 24);
    pack_w2_kernel<<<(4 * 120 * 4 + 255) / 256, 256>>>(r1w2, w4p1, 120);

    init_nodes_kernel<<<NB72, 256>>>(x, embed_w, hA);

    radial_tc_kernel<24><<<EDGESN / 128, 256, sh24>>>(ev, r0w1, r0b1, w4p0, r0b2, w0);
    tp_first_kernel<<<EDGESN * 8 / 256, 256>>>(hA, src, epos, ev, w0, hb);
    updateA_kernel<<<NGB, 288>>>(hb, rowptr, hA, lin0, hB);

    radial_tc_kernel<120><<<EDGESN / 128, 256, sh120>>>(ev, r1w1, r1b1, w4p1, r1b2, w1);
    tp_uuu_kernel<<<EDGESN * 8 / 256, 256>>>(hB, src, epos, w1, hb);
    updateB_kernel<<<NGB, 288>>>(hb, rowptr, hB, lin1, hA);

    tp_uuu_kernel<<<EDGESN * 8 / 256, 256>>>(hA, src, epos, w2, hb);
    updateB_kernel<<<NGB, 288>>>(hb, rowptr, hA, lin2, hB);

    readout_kernel<<<(NODESN + 255) / 256, 256>>>(hB, out_w, out);
}

// round 15
// speedup vs baseline: 1.1007x; 1.0819x over previous
#include <cuda_runtime.h>
#include <cuda_bf16.h>
#include <math.h>
#include <stdint.h>

#define NODESN 40000
#define EDGESN 640000

// ---------------- static device scratch ----------------
__device__ float g_CG[15 * 125];
__device__ float g_hA[NODESN * 72];
__device__ float g_hB[NODESN * 72];
__device__ float g_hb[EDGESN * 72];     // messages, CSR slot order
__device__ float g_w0[EDGESN * 24];     // radial outputs, CSR-pos fragment order
__device__ float g_w1[EDGESN * 120];
__device__ float g_w2[EDGESN * 120];
__device__ float2 g_w2p0[8 * 24 * 4];   // packed tf32 W2, layer0 (OD=24)
__device__ float2 g_w2p1[8 * 120 * 4];  // layer1
__device__ float2 g_w2p2[8 * 120 * 4];  // layer2
__device__ int   g_cnt[NODESN];
__device__ int   g_rowptr[NODESN + 1];
__device__ int   g_cursor[NODESN];
__device__ int   g_perm[EDGESN];        // perm[pos] = edge id
__device__ int   g_srcp[EDGESN];        // srcp[pos] = src[perm[pos]]
__device__ int   g_bsum[64];

// ---------------- CG init (values computed in fp64 on device) ----------------
__device__ double dfact(int n) {
    const double f[9] = {1.,1.,2.,6.,24.,120.,720.,5040.,40320.};
    return f[n];
}
__device__ double dclebsch(int j1,int m1,int j2,int m2,int j3,int m3) {
    if (m1 + m2 != m3) return 0.0;
    double pref = sqrt((2.0*j3+1.0)*dfact(j3+j1-j2)*dfact(j3-j1+j2)*dfact(j1+j2-j3)/dfact(j1+j2+j3+1));
    pref *= sqrt(dfact(j3+m3)*dfact(j3-m3)*dfact(j1-m1)*dfact(j1+m1)*dfact(j2-m2)*dfact(j2+m2));
    int lo = max(0, max(j2-j3-m1, j1-j3+m2));
    int hi = min(j1+j2-j3, min(j1-m1, j2+m2));
    double s = 0.0;
    for (int k = lo; k <= hi; k++) {
        double d = dfact(k)*dfact(j1+j2-j3-k)*dfact(j1-m1-k)*dfact(j2+m2-k)*dfact(j3-j2+m1+k)*dfact(j3-j1-m2+k);
        s += ((k & 1) ? -1.0 : 1.0) / d;
    }
    return pref * s;
}
__device__ void u_elem(int l, int row, int col, double* re, double* im) {
    int m = row - l;
    const double s2 = 0.7071067811865476;
    double r = 0.0, ii = 0.0;
    double sgn = (m & 1) ? -1.0 : 1.0;
    if (m > 0) {
        if (col == m + l) r = sgn * s2;
        else if (col == l - m) r = s2;
    } else if (m == 0) {
        if (col == l) r = 1.0;
    } else {
        if (col == m + l) ii = s2;
        else if (col == l - m) ii = -sgn * s2;
    }
    *re = r; *im = ii;
}
__constant__ int c_P[15][3] = {{0,0,0},{0,1,1},{0,2,2},{1,0,1},{1,1,0},{1,1,1},{1,1,2},
                               {1,2,1},{1,2,2},{2,0,2},{2,1,1},{2,1,2},{2,2,0},{2,2,1},{2,2,2}};

__global__ void cg_init_kernel() {
    int p = blockIdx.x;
    int l1 = c_P[p][0], l2 = c_P[p][1], l3 = c_P[p][2];
    int d1 = 2*l1+1, d2 = 2*l2+1, d3 = 2*l3+1;
    int t = threadIdx.x;                 // 0..124
    int a = t / 25, b = (t / 5) % 5, c = t % 5;
    double tre = 0.0, tim = 0.0;
    bool inr = (a < d1 && b < d2 && c < d3);
    if (inr) {
        for (int m = 0; m < d1; m++) {
            double u1r, u1i; u_elem(l1, a, m, &u1r, &u1i); u1i = -u1i;
            if (u1r == 0.0 && u1i == 0.0) continue;
            for (int n = 0; n < d2; n++) {
                double u2r, u2i; u_elem(l2, b, n, &u2r, &u2i); u2i = -u2i;
                if (u2r == 0.0 && u2i == 0.0) continue;
                int m3 = (m - l1) + (n - l2);
                if (m3 < -l3 || m3 > l3) continue;
                int o = m3 + l3;
                double u3r, u3i; u_elem(l3, c, o, &u3r, &u3i);
                if (u3r == 0.0 && u3i == 0.0) continue;
                double cv = dclebsch(l1, m-l1, l2, n-l2, l3, m3);
                if (cv == 0.0) continue;
                double pr = u1r*u2r - u1i*u2i;
                double pi = u1r*u2i + u1i*u2r;
                tre += (pr*u3r - pi*u3i) * cv;
                tim += (pr*u3i + pi*u3r) * cv;
            }
        }
    }
    __shared__ double sre[125], sim[125];
    __shared__ int useim;
    sre[t] = fabs(tre); sim[t] = fabs(tim);
    __syncthreads();
    if (t == 0) {
        double mr = 0.0, mi = 0.0;
        for (int q = 0; q < 125; q++) { mr = fmax(mr, sre[q]); mi = fmax(mi, sim[q]); }
        useim = (mi > mr) ? 1 : 0;
    }
    __syncthreads();
    g_CG[p * 125 + t] = inr ? (float)(useim ? tim : tre) : 0.0f;
}

// compile-time superset of real-CG sparsity (values still from g_CG, so superset is safe)
__host__ __device__ constexpr bool cg_ok(int l1,int l2,int l3,int i,int j,int k){
    int m1=i-l1, m2=j-l2, m3=k-l3;
    int a1=m1<0?-m1:m1, a2=m2<0?-m2:m2, a3=m3<0?-m3:m3;
    int s=a1+a2, d=(a1>a2)?(a1-a2):(a2-a1);
    if (a3!=s && a3!=d) return false;
    int neg=(m1<0)+(m2<0)+(m3<0);
    return ((neg&1)==((l1+l2+l3)&1));
}

// ---------------- CSR build ----------------
__global__ void hist_zero_kernel(int* __restrict__ cnt) {
    int i = blockIdx.x * blockDim.x + threadIdx.x;
    if (i < NODESN) cnt[i] = 0;
}
__global__ void hist_kernel(const int* __restrict__ dst, int* __restrict__ cnt) {
    int e = blockIdx.x * blockDim.x + threadIdx.x;
    if (e < EDGESN) atomicAdd(&cnt[dst[e]], 1);
}
__global__ void scan1_kernel(const int* __restrict__ cnt, int* __restrict__ rowptr,
                             int* __restrict__ bsum) {
    __shared__ int tmp[1024];
    int t = threadIdx.x;
    int i = blockIdx.x * 1024 + t;
    int v = (i < NODESN) ? cnt[i] : 0;
    tmp[t] = v;
    __syncthreads();
    for (int off = 1; off < 1024; off <<= 1) {
        int add = (t >= off) ? tmp[t - off] : 0;
        __syncthreads();
        tmp[t] += add;
        __syncthreads();
    }
    if (i < NODESN) rowptr[i + 1] = tmp[t];
    if (t == 1023) bsum[blockIdx.x] = tmp[1023];
}
__global__ void scan2_kernel(int* __restrict__ bsum, int nb) {
    if (threadIdx.x == 0) {
        int run = 0;
        for (int b = 0; b < nb; b++) { int s = bsum[b]; bsum[b] = run; run += s; }
    }
}
__global__ void scan3_kernel(const int* __restrict__ cnt, int* __restrict__ rowptr,
                             int* __restrict__ cursor, const int* __restrict__ bsum) {
    int i = blockIdx.x * 1024 + threadIdx.x;
    if (i < NODESN) {
        int incl = rowptr[i + 1] + bsum[blockIdx.x];
        rowptr[i + 1] = incl;
        cursor[i] = incl - cnt[i];
    }
    if (i == 0) rowptr[0] = 0;
}
__global__ void scatter_kernel(const int* __restrict__ dst, const int* __restrict__ src,
                               int* __restrict__ cursor, int* __restrict__ perm,
                               int* __restrict__ srcp) {
    int e = blockIdx.x * blockDim.x + threadIdx.x;
    if (e >= EDGESN) return;
    int pos = atomicAdd(&cursor[dst[e]], 1);
    perm[pos] = e;
    srcp[pos] = src[e];
}

// ---------------- node init ----------------
__global__ void init_nodes_kernel(const int* __restrict__ x, const float* __restrict__ embed_w,
                                  float* __restrict__ hA) {
    int idx = blockIdx.x * blockDim.x + threadIdx.x;
    if (idx >= NODESN * 72) return;
    int n = idx / 72, pos = idx - n * 72;
    hA[idx] = (pos < 8) ? embed_w[x[n] * 8 + pos] : 0.0f;
}

// ---------------- radial MLP with TF32 tensor-core second GEMM ----------------
// Processes CSR slots: slot p in [blockIdx*128, +128), edge id = perm[p].
// Output layout FRAGMENT-NATIVE indexed by slot p: per 128-slot block, per 16x8
// tile (mtile, nt): element (r, n=nt*8+nn): lane=(r&7)*4+(nn>>1), reg=(r>>3)*2+(nn&1)
__device__ __forceinline__ float to_tf32(float x) {
    uint32_t u;
    asm("cvt.rna.tf32.f32 %0, %1;" : "=r"(u) : "f"(x));
    return __uint_as_float(u);
}

#define HSTR 136   // 136 mod 32 == 8 -> A-fragment LDS conflict-free

// pack W2 (tf32-rounded) into B-fragment order:
// out[(kc*OD + n)*4 + qc] = { W2[(kc*8+qc)*OD+n], W2[(kc*8+qc+4)*OD+n] }
__global__ void pack_w2_kernel(const float* __restrict__ W2, float2* __restrict__ out, int OD) {
    int idx = blockIdx.x * blockDim.x + threadIdx.x;
    if (idx >= 8 * OD * 4) return;
    int kc = idx / (OD * 4);
    int rem = idx - kc * OD * 4;
    int n = rem >> 2, qc = rem & 3;
    out[idx] = make_float2(to_tf32(W2[(kc * 8 + qc) * OD + n]),
                           to_tf32(W2[(kc * 8 + qc + 4) * OD + n]));
}

// one pass: NT n-tiles starting at ntb; accumulators NT*4 regs
template<int OD, int NT>
__device__ __forceinline__ void mma_pass(const float* hidT, const float2* __restrict__ W2p,
                                         const float* B2s, float* woutb,
                                         int ntb, int m0, int warp, int lane) {
    constexpr int NTall = OD / 8;
    int qr = lane >> 2, qc = lane & 3;
    float c0[NT], c1[NT], c2[NT], c3[NT];
    #pragma unroll
    for (int n = 0; n < NT; n++) { c0[n]=0.f; c1[n]=0.f; c2[n]=0.f; c3[n]=0.f; }
    #pragma unroll
    for (int kc = 0; kc < 8; kc++) {
        int kA = kc * 8 + qc;
        uint32_t a0 = __float_as_uint(hidT[kA * HSTR + m0 + qr]);
        uint32_t a1 = __float_as_uint(hidT[kA * HSTR + m0 + qr + 8]);
        uint32_t a2 = __float_as_uint(hidT[(kA + 4) * HSTR + m0 + qr]);
        uint32_t a3 = __float_as_uint(hidT[(kA + 4) * HSTR + m0 + qr + 8]);
        #pragma unroll
        for (int nt = 0; nt < NT; nt++) {
            float2 bv = __ldg(&W2p[(kc * OD + (ntb + nt) * 8) * 4 + qr * 4 + qc]);
            uint32_t b0 = __float_as_uint(bv.x);
            uint32_t b1 = __float_as_uint(bv.y);
            asm volatile("mma.sync.aligned.m16n8k8.row.col.f32.tf32.tf32.f32 "
                         "{%0,%1,%2,%3}, {%4,%5,%6,%7}, {%8,%9}, {%0,%1,%2,%3};"
                         : "+f"(c0[nt]), "+f"(c1[nt]), "+f"(c2[nt]), "+f"(c3[nt])
                         : "r"(a0), "r"(a1), "r"(a2), "r"(a3), "r"(b0), "r"(b1));
        }
    }
    #pragma unroll
    for (int nt = 0; nt < NT; nt++) {
        int n0 = (ntb + nt) * 8 + qc * 2;
        float4 v = make_float4(c0[nt] + B2s[n0], c1[nt] + B2s[n0 + 1],
                               c2[nt] + B2s[n0], c3[nt] + B2s[n0 + 1]);
        *(float4*)&woutb[(size_t)(warp * NTall + ntb + nt) * 128 + lane * 4] = v;
    }
}

template<int OD>
__global__ void __launch_bounds__(256, 4) radial_tc_kernel(
                                 const float* __restrict__ ev, const int* __restrict__ perm,
                                 const float* __restrict__ W1, const float* __restrict__ B1,
                                 const float2* __restrict__ W2p, const float* __restrict__ B2,
                                 float* __restrict__ Wout) {
    extern __shared__ float sm[];
    float* W1s  = sm;                    // 16*64
    float* B1s  = W1s + 1024;            // 64
    float* B2s  = B1s + 64;              // OD
    float* hidT = B2s + OD;              // [64][HSTR] tf32-rounded
    int t = threadIdx.x;
    int p0 = blockIdx.x * 128;
    for (int i = t; i < 1024;   i += 256) W1s[i] = W1[i];
    for (int i = t; i < 64;     i += 256) B1s[i] = B1[i];
    for (int i = t; i < OD;     i += 256) B2s[i] = B2[i];
    __syncthreads();
    // hidden layer: soft-onehot has at most 2 active bins -> 2 FMAs per hidden unit
    {
        int p = t & 127;
        int hg = t >> 7;
        int eg = __ldg(&perm[p0 + p]);
        float x = __ldg(&ev[eg * 3]), y = __ldg(&ev[eg * 3 + 1]), z = __ldg(&ev[eg * 3 + 2]);
        float r = sqrtf(x*x + y*y + z*z + 1e-12f);
        float q = r * (17.0f / 3.0f);           // r/step, step = 3/17
        int ib = (int)floorf(q);
        float f0 = 0.0f, f1 = 0.0f;
        int r0 = 0, r1 = 0;
        {
            int b = ib;
            if (b >= 1 && b <= 16) {
                float d = q - (float)b;
                if (fabsf(d) < 1.0f) { f0 = 8.4335731f * __expf(-2.0f / (1.0f - d * d)); r0 = b - 1; }
            }
            b = ib + 1;
            if (b >= 1 && b <= 16) {
                float d = q - (float)b;
                if (fabsf(d) < 1.0f) { f1 = 8.4335731f * __expf(-2.0f / (1.0f - d * d)); r1 = b - 1; }
            }
        }
        const float* w1r0 = &W1s[r0 * 64];
        const float* w1r1 = &W1s[r1 * 64];
        #pragma unroll
        for (int j = 0; j < 32; j++) {
            int h = hg * 32 + j;
            float acc = B1s[h] + f0 * w1r0[h] + f1 * w1r1[h];
            acc = acc / (1.0f + __expf(-acc));
            hidT[h * HSTR + p] = to_tf32(acc);
        }
    }
    __syncthreads();
    // second GEMM 128 x OD x 64: warp -> 1 m-tile, two accumulator passes over n
    {
        constexpr int NTT = OD / 8;
        constexpr int NT0 = (NTT + 1) / 2;
        constexpr int NT1 = NTT - NT0;
        int warp = t >> 5, lane = t & 31;
        int m0 = warp * 16;
        float* woutb = Wout + (size_t)blockIdx.x * (128 * OD);
        mma_pass<OD, NT0>(hidT, W2p, B2s, woutb, 0,   m0, warp, lane);
        if (NT1 > 0)
            mma_pass<OD, NT1>(hidT, W2p, B2s, woutb, NT0, m0, warp, lane);
    }
}

// ---------------- tp_first: slot-ordered, linear m writes ----------------
__global__ void tp_first_kernel(const float* __restrict__ h, const int* __restrict__ perm,
                                const int* __restrict__ srcp, const float* __restrict__ ev,
                                const float* __restrict__ w, float* __restrict__ m) {
    int gid = blockIdx.x * blockDim.x + threadIdx.x;
    int pos = gid >> 3, c = gid & 7;
    if (pos >= EDGESN) return;
    int e = __ldg(&perm[pos]);
    int s = __ldg(&srcp[pos]);
    float x = __ldg(&ev[e*3]), y = __ldg(&ev[e*3+1]), z = __ldg(&ev[e*3+2]);
    float r = sqrtf(x*x + y*y + z*z + 1e-12f);
    float inv = 1.0f / r; x *= inv; y *= inv; z *= inv;
    const float c3 = 1.7320508076f, c15 = 3.8729833462f, c5 = 2.2360679775f;
    float sh1[3] = { c3*y, c3*z, c3*x };
    float sh2[5] = { c15*x*y, c15*y*z, 0.5f*c5*(3.0f*z*z-1.0f), c15*x*z, 0.5f*c15*(x*x-y*y) };
    float hs = h[s * 72 + c];
    int pL = pos & 127;
    int mtile = pL >> 4, rr = pL & 15;
    int lane = (rr & 7) * 4 + (c >> 1);
    int reg = ((rr >> 3) << 1) + (c & 1);
    const float* wb = &w[(size_t)(pos >> 7) * 3072 + (size_t)mtile * 384 + lane * 4 + reg];
    float w0 = wb[0], w1v = wb[128], w2v = wb[256];
    float* mp = &m[(size_t)pos * 72];
    mp[c] = w0 * hs;
    float hv = w1v * hs, ht = w2v * hs;
    #pragma unroll
    for (int i = 0; i < 3; i++) mp[8 + c*3 + i] = hv * sh1[i];
    #pragma unroll
    for (int j = 0; j < 5; j++) mp[32 + c*5 + j] = ht * sh2[j];
}

// ---------------- fused streaming gather + update A ----------------
__global__ void updateA_kernel(const float* __restrict__ m, const int* __restrict__ row_ptr,
                               const float* __restrict__ hin, const float* __restrict__ lin0,
                               float* __restrict__ hout) {
    int node = blockIdx.x * 4 + threadIdx.x / 72;
    int k = threadIdx.x % 72;
    if (node >= NODESN || threadIdx.x >= 288) return;
    int beg = row_ptr[node], end = row_ptr[node + 1];
    float acc = 0.0f;
    #pragma unroll 4
    for (int j = beg; j < end; j++) acc += m[(size_t)j * 72 + k];
    float v = acc * 0.25f;
    if (k < 8) {
        float a2 = 0.0f;
        #pragma unroll
        for (int c = 0; c < 8; c++) a2 += hin[node * 72 + c] * lin0[c * 8 + k];
        v += a2 * 0.35355339059f;
        v = v / (1.0f + __expf(-v));
    }
    hout[node * 72 + k] = v;
}

// ---------------- tp_uuu: slot-ordered, linear hb/w access ----------------
__global__ void tp_uuu_kernel(const float* __restrict__ h, const int* __restrict__ srcp,
                              const float* __restrict__ w, float* __restrict__ hb) {
    __shared__ float CGs[15 * 125];
    for (int i = threadIdx.x; i < 1875; i += 256) CGs[i] = g_CG[i];
    __syncthreads();
    int gid = blockIdx.x * 256 + threadIdx.x;
    int pos = gid >> 3, c = gid & 7;
    if (pos >= EDGESN) return;
    int s = __ldg(&srcp[pos]);
    const float* hp = &h[s * 72];
    float A0[1], A1[3], A2[5], B0[1], B1[3], B2[5];
    A0[0] = hp[c];
    #pragma unroll
    for (int i = 0; i < 3; i++) A1[i] = hp[8 + c*3 + i];
    #pragma unroll
    for (int j = 0; j < 5; j++) A2[j] = hp[32 + c*5 + j];
    float* bp = &hb[(size_t)pos * 72];
    float b0raw = bp[c];
    B0[0] = b0raw / (1.0f + __expf(-b0raw));   // act() applied on consume
    #pragma unroll
    for (int i = 0; i < 3; i++) B1[i] = bp[8 + c*3 + i];
    #pragma unroll
    for (int j = 0; j < 5; j++) B2[j] = bp[32 + c*5 + j];
    // fragment-native w read (slot-indexed)
    float wp[15];
    {
        int pL = pos & 127;
        int mtile = pL >> 4, rr = pL & 15;
        int lane = (rr & 7) * 4 + (c >> 1);
        int reg = ((rr >> 3) << 1) + (c & 1);
        const float* wb = &w[(size_t)(pos >> 7) * 15360 + (size_t)mtile * 1920 + lane * 4 + reg];
        #pragma unroll
        for (int p = 0; p < 15; p++) wp[p] = wb[p * 128];
    }
    float O0[1] = {0.f}, O1[3] = {0.f,0.f,0.f}, O2[5] = {0.f,0.f,0.f,0.f,0.f};

#define DOPATH(P, L1, L2, L3, AR, BR, OR, D1, D2, D3) { \
    const float* cg = &CGs[(P) * 125]; float wl = wp[P]; \
    _Pragma("unroll") for (int i = 0; i < (D1); i++) { float aw = AR[i] * wl; \
        _Pragma("unroll") for (int j = 0; j < (D2); j++) { float ab = aw * BR[j]; \
            _Pragma("unroll") for (int k = 0; k < (D3); k++) { \
                if (cg_ok(L1,L2,L3,i,j,k)) OR[k] += ab * cg[i*25 + j*5 + k]; } } } }

    DOPATH(0,  0,0,0, A0, B0, O0, 1, 1, 1)
    DOPATH(1,  0,1,1, A0, B1, O1, 1, 3, 3)
    DOPATH(2,  0,2,2, A0, B2, O2, 1, 5, 5)
    DOPATH(3,  1,0,1, A1, B0, O1, 3, 1, 3)
    DOPATH(4,  1,1,0, A1, B1, O0, 3, 3, 1)
    DOPATH(5,  1,1,1, A1, B1, O1, 3, 3, 3)
    DOPATH(6,  1,1,2, A1, B1, O2, 3, 3, 5)
    DOPATH(7,  1,2,1, A1, B2, O1, 3, 5, 3)
    DOPATH(8,  1,2,2, A1, B2, O2, 3, 5, 5)
    DOPATH(9,  2,0,2, A2, B0, O2, 5, 1, 5)
    DOPATH(10, 2,1,1, A2, B1, O1, 5, 3, 3)
    DOPATH(11, 2,1,2, A2, B1, O2, 5, 3, 5)
    DOPATH(12, 2,2,0, A2, B2, O0, 5, 5, 1)
    DOPATH(13, 2,2,1, A2, B2, O1, 5, 5, 3)
    DOPATH(14, 2,2,2, A2, B2, O2, 5, 5, 5)
#undef DOPATH

    const float n0 = 0.57735026919f, n12 = 0.40824829046f;
    bp[c] = O0[0] * n0;
    #pragma unroll
    for (int i = 0; i < 3; i++) bp[8 + c*3 + i] = O1[i] * n12;
    #pragma unroll
    for (int j = 0; j < 5; j++) bp[32 + c*5 + j] = O2[j] * n12;
}

// ---------------- fused streaming gather + update B ----------------
__global__ void updateB_kernel(const float* __restrict__ m, const int* __restrict__ row_ptr,
                               const float* __restrict__ hin, const float* __restrict__ lin,
                               float* __restrict__ hout) {
    int node = blockIdx.x * 4 + threadIdx.x / 72;
    int k = threadIdx.x % 72;
    if (node >= NODESN || threadIdx.x >= 288) return;
    int beg = row_ptr[node], end = row_ptr[node + 1];
    float acc = 0.0f;
    #pragma unroll 4
    for (int j = beg; j < end; j++) acc += m[(size_t)j * 72 + k];
    float v = acc * 0.25f;
    const float* hp = &hin[node * 72];
    const float R8 = 0.35355339059f;
    float a2 = 0.0f;
    if (k < 8) {
        #pragma unroll
        for (int c = 0; c < 8; c++) a2 += hp[c] * lin[c * 8 + k];
        v += a2 * R8;
        v = v / (1.0f + __expf(-v));
    } else if (k < 32) {
        int dd = (k - 8) / 3, i = (k - 8) % 3;
        #pragma unroll
        for (int c = 0; c < 8; c++) a2 += hp[8 + c*3 + i] * lin[64 + c * 8 + dd];
        v += a2 * R8;
    } else {
        int dd = (k - 32) / 5, j2 = (k - 32) % 5;
        #pragma unroll
        for (int c = 0; c < 8; c++) a2 += hp[32 + c*5 + j2] * lin[128 + c * 8 + dd];
        v += a2 * R8;
    }
    hout[node * 72 + k] = v;
}

// ---------------- readout ----------------
__global__ void readout_kernel(const float* __restrict__ h, const float* __restrict__ ow,
                               float* __restrict__ out) {
    __shared__ float W[1536];
    for (int i = threadIdx.x; i < 1536; i += 256) W[i] = ow[i];
    __syncthreads();
    int n = blockIdx.x * blockDim.x + threadIdx.x;
    if (n >= NODESN) return;
    const float* hp = &h[n * 72];
    float hs[72];
    #pragma unroll
    for (int i = 0; i < 72; i++) hs[i] = hp[i];
    float acc[8] = {0,0,0,0,0,0,0,0};
    const float i1n = 0.57735026919f, i2n = 0.44721359550f;
    #pragma unroll
    for (int i = 0; i < 8; i++) {
        #pragma unroll
        for (int j = 0; j < 8; j++) {
            float p0 = hs[i] * hs[j];
            float p1 = (hs[8+i*3]*hs[8+j*3] + hs[9+i*3]*hs[9+j*3] + hs[10+i*3]*hs[10+j*3]) * i1n;
            float p2 = 0.0f;
            #pragma unroll
            for (int q = 0; q < 5; q++) p2 += hs[32+i*5+q] * hs[32+j*5+q];
            p2 *= i2n;
            int base = (i * 8 + j) * 8;
            #pragma unroll
            for (int k = 0; k < 8; k++)
                acc[k] += p0 * W[base + k] + p1 * W[512 + base + k] + p2 * W[1024 + base + k];
        }
    }
    const float fn = 0.07216878365f;  // 1/sqrt(192)
    #pragma unroll
    for (int k = 0; k < 8; k++) out[n * 8 + k] = acc[k] * fn;
}

// ---------------- launch ----------------
extern "C" void kernel_launch(void* const* d_in, const int* in_sizes, int n_in,
                              void* d_out, int out_size) {
    const int*   x       = (const int*)d_in[0];
    const int*   ei      = (const int*)d_in[1];
    const float* ev      = (const float*)d_in[2];
    const float* embed_w = (const float*)d_in[3];
    const float* lin0    = (const float*)d_in[4];
    const float* lin1    = (const float*)d_in[5];
    const float* lin2    = (const float*)d_in[6];
    const float* out_w   = (const float*)d_in[7];
    const float* r0w1 = (const float*)d_in[8],  *r0b1 = (const float*)d_in[9];
    const float* r0w2 = (const float*)d_in[10], *r0b2 = (const float*)d_in[11];
    const float* r1w1 = (const float*)d_in[12], *r1b1 = (const float*)d_in[13];
    const float* r1w2 = (const float*)d_in[14], *r1b2 = (const float*)d_in[15];
    const float* r2w1 = (const float*)d_in[16], *r2b1 = (const float*)d_in[17];
    const float* r2w2 = (const float*)d_in[18], *r2b2 = (const float*)d_in[19];
    float* out = (float*)d_out;
    const int* src = ei;
    const int* dst = ei + EDGESN;

    float *hA, *hB, *hb, *w0, *w1, *w2;
    float2 *w2p0, *w2p1, *w2p2;
    int *cnt, *rowptr, *cursor, *perm, *srcp, *bsum;
    cudaGetSymbolAddress((void**)&hA, g_hA);
    cudaGetSymbolAddress((void**)&hB, g_hB);
    cudaGetSymbolAddress((void**)&hb, g_hb);
    cudaGetSymbolAddress((void**)&w0, g_w0);
    cudaGetSymbolAddress((void**)&w1, g_w1);
    cudaGetSymbolAddress((void**)&w2, g_w2);
    cudaGetSymbolAddress((void**)&w2p0, g_w2p0);
    cudaGetSymbolAddress((void**)&w2p1, g_w2p1);
    cudaGetSymbolAddress((void**)&w2p2, g_w2p2);
    cudaGetSymbolAddress((void**)&cnt, g_cnt);
    cudaGetSymbolAddress((void**)&rowptr, g_rowptr);
    cudaGetSymbolAddress((void**)&cursor, g_cursor);
    cudaGetSymbolAddress((void**)&perm, g_perm);
    cudaGetSymbolAddress((void**)&srcp, g_srcp);
    cudaGetSymbolAddress((void**)&bsum, g_bsum);

    size_t sh24  = (size_t)(1024 + 64 + 24 + 64*HSTR) * 4;    // 39264 B
    size_t sh120 = (size_t)(1024 + 64 + 120 + 64*HSTR) * 4;   // 39648 B
    cudaFuncSetAttribute(radial_tc_kernel<24>,  cudaFuncAttributeMaxDynamicSharedMemorySize, (int)sh24);
    cudaFuncSetAttribute(radial_tc_kernel<120>, cudaFuncAttributeMaxDynamicSharedMemorySize, (int)sh120);

    const int NB72 = (NODESN * 72 + 255) / 256;
    const int NGB  = (NODESN + 3) / 4;
    const int NSCAN = (NODESN + 1023) / 1024;     // 40

    // CSR build must precede radial kernels now (they gather via perm)
    cg_init_kernel<<<15, 125>>>();
    hist_zero_kernel<<<(NODESN + 255) / 256, 256>>>(cnt);
    hist_kernel<<<(EDGESN + 255) / 256, 256>>>(dst, cnt);
    scan1_kernel<<<NSCAN, 1024>>>(cnt, rowptr, bsum);
    scan2_kernel<<<1, 32>>>(bsum, NSCAN);
    scan3_kernel<<<NSCAN, 1024>>>(cnt, rowptr, cursor, bsum);
    scatter_kernel<<<(EDGESN + 255) / 256, 256>>>(dst, src, cursor, perm, srcp);
    pack_w2_kernel<<<(8 * 120 * 4 + 255) / 256, 256>>>(r2w2, w2p2, 120);
    radial_tc_kernel<120><<<EDGESN / 128, 256, sh120>>>(ev, perm, r2w1, r2b1, w2p2, r2b2, w2);
    pack_w2_kernel<<<(8 * 24 * 4 + 255) / 256, 256>>>(r0w2, w2p0, 24);
    pack_w2_kernel<<<(8 * 120 * 4 + 255) / 256, 256>>>(r1w2, w2p1, 120);

    init_nodes_kernel<<<NB72, 256>>>(x, embed_w, hA);

    radial_tc_kernel<24><<<EDGESN / 128, 256, sh24>>>(ev, perm, r0w1, r0b1, w2p0, r0b2, w0);
    tp_first_kernel<<<EDGESN * 8 / 256, 256>>>(hA, perm, srcp, ev, w0, hb);
    updateA_kernel<<<NGB, 288>>>(hb, rowptr, hA, lin0, hB);

    radial_tc_kernel<120><<<EDGESN / 128, 256, sh120>>>(ev, perm, r1w1, r1b1, w2p1, r1b2, w1);
    tp_uuu_kernel<<<EDGESN * 8 / 256, 256>>>(hB, srcp, w1, hb);
    updateB_kernel<<<NGB, 288>>>(hb, rowptr, hB, lin1, hA);

    tp_uuu_kernel<<<EDGESN * 8 / 256, 256>>>(hA, srcp, w2, hb);
    updateB_kernel<<<NGB, 288>>>(hb, rowptr, hA, lin2, hB);

    readout_kernel<<<(NODESN + 255) / 256, 256>>>(hB, out_w, out);
}

// round 16
// speedup vs baseline: 1.1153x; 1.0133x over previous
#include <cuda_runtime.h>
#include <cuda_bf16.h>
#include <math.h>
#include <stdint.h>

#define NODESN 40000
#define EDGESN 640000

// ---------------- static device scratch ----------------
__device__ float g_CG[15 * 125];
__device__ float g_hA[NODESN * 72];
__device__ float g_hB[NODESN * 72];
__device__ float g_hb[EDGESN * 72];     // messages, CSR slot order
__device__ float g_w0[EDGESN * 24];     // radial outputs, CSR-pos fragment order
__device__ float g_w1[EDGESN * 120];
__device__ float g_w2[EDGESN * 120];
__device__ float2 g_w2p0[8 * 24 * 4];   // packed tf32 W2, layer0 (OD=24)
__device__ float2 g_w2p1[8 * 120 * 4];  // layer1
__device__ float2 g_w2p2[8 * 120 * 4];  // layer2
__device__ int   g_cnt[NODESN];
__device__ int   g_rowptr[NODESN + 1];
__device__ int   g_cursor[NODESN];
__device__ int   g_perm[EDGESN];        // perm[pos] = edge id
__device__ int   g_srcp[EDGESN];        // srcp[pos] = src[perm[pos]]
__device__ int   g_bsum[64];

// ---------------- CG init (values computed in fp64 on device) ----------------
__device__ double dfact(int n) {
    const double f[9] = {1.,1.,2.,6.,24.,120.,720.,5040.,40320.};
    return f[n];
}
__device__ double dclebsch(int j1,int m1,int j2,int m2,int j3,int m3) {
    if (m1 + m2 != m3) return 0.0;
    double pref = sqrt((2.0*j3+1.0)*dfact(j3+j1-j2)*dfact(j3-j1+j2)*dfact(j1+j2-j3)/dfact(j1+j2+j3+1));
    pref *= sqrt(dfact(j3+m3)*dfact(j3-m3)*dfact(j1-m1)*dfact(j1+m1)*dfact(j2-m2)*dfact(j2+m2));
    int lo = max(0, max(j2-j3-m1, j1-j3+m2));
    int hi = min(j1+j2-j3, min(j1-m1, j2+m2));
    double s = 0.0;
    for (int k = lo; k <= hi; k++) {
        double d = dfact(k)*dfact(j1+j2-j3-k)*dfact(j1-m1-k)*dfact(j2+m2-k)*dfact(j3-j2+m1+k)*dfact(j3-j1-m2+k);
        s += ((k & 1) ? -1.0 : 1.0) / d;
    }
    return pref * s;
}
__device__ void u_elem(int l, int row, int col, double* re, double* im) {
    int m = row - l;
    const double s2 = 0.7071067811865476;
    double r = 0.0, ii = 0.0;
    double sgn = (m & 1) ? -1.0 : 1.0;
    if (m > 0) {
        if (col == m + l) r = sgn * s2;
        else if (col == l - m) r = s2;
    } else if (m == 0) {
        if (col == l) r = 1.0;
    } else {
        if (col == m + l) ii = s2;
        else if (col == l - m) ii = -sgn * s2;
    }
    *re = r; *im = ii;
}
__constant__ int c_P[15][3] = {{0,0,0},{0,1,1},{0,2,2},{1,0,1},{1,1,0},{1,1,1},{1,1,2},
                               {1,2,1},{1,2,2},{2,0,2},{2,1,1},{2,1,2},{2,2,0},{2,2,1},{2,2,2}};

__global__ void cg_init_kernel() {
    int p = blockIdx.x;
    int l1 = c_P[p][0], l2 = c_P[p][1], l3 = c_P[p][2];
    int d1 = 2*l1+1, d2 = 2*l2+1, d3 = 2*l3+1;
    int t = threadIdx.x;                 // 0..124
    int a = t / 25, b = (t / 5) % 5, c = t % 5;
    double tre = 0.0, tim = 0.0;
    bool inr = (a < d1 && b < d2 && c < d3);
    if (inr) {
        for (int m = 0; m < d1; m++) {
            double u1r, u1i; u_elem(l1, a, m, &u1r, &u1i); u1i = -u1i;
            if (u1r == 0.0 && u1i == 0.0) continue;
            for (int n = 0; n < d2; n++) {
                double u2r, u2i; u_elem(l2, b, n, &u2r, &u2i); u2i = -u2i;
                if (u2r == 0.0 && u2i == 0.0) continue;
                int m3 = (m - l1) + (n - l2);
                if (m3 < -l3 || m3 > l3) continue;
                int o = m3 + l3;
                double u3r, u3i; u_elem(l3, c, o, &u3r, &u3i);
                if (u3r == 0.0 && u3i == 0.0) continue;
                double cv = dclebsch(l1, m-l1, l2, n-l2, l3, m3);
                if (cv == 0.0) continue;
                double pr = u1r*u2r - u1i*u2i;
                double pi = u1r*u2i + u1i*u2r;
                tre += (pr*u3r - pi*u3i) * cv;
                tim += (pr*u3i + pi*u3r) * cv;
            }
        }
    }
    __shared__ double sre[125], sim[125];
    __shared__ int useim;
    sre[t] = fabs(tre); sim[t] = fabs(tim);
    __syncthreads();
    if (t == 0) {
        double mr = 0.0, mi = 0.0;
        for (int q = 0; q < 125; q++) { mr = fmax(mr, sre[q]); mi = fmax(mi, sim[q]); }
        useim = (mi > mr) ? 1 : 0;
    }
    __syncthreads();
    g_CG[p * 125 + t] = inr ? (float)(useim ? tim : tre) : 0.0f;
}

// compile-time superset of real-CG sparsity (values still from g_CG, so superset is safe)
__host__ __device__ constexpr bool cg_ok(int l1,int l2,int l3,int i,int j,int k){
    int m1=i-l1, m2=j-l2, m3=k-l3;
    int a1=m1<0?-m1:m1, a2=m2<0?-m2:m2, a3=m3<0?-m3:m3;
    int s=a1+a2, d=(a1>a2)?(a1-a2):(a2-a1);
    if (a3!=s && a3!=d) return false;
    int neg=(m1<0)+(m2<0)+(m3<0);
    return ((neg&1)==((l1+l2+l3)&1));
}

// ---------------- CSR build ----------------
__global__ void hist_zero_kernel(int* __restrict__ cnt) {
    int i = blockIdx.x * blockDim.x + threadIdx.x;
    if (i < NODESN) cnt[i] = 0;
}
__global__ void hist_kernel(const int* __restrict__ dst, int* __restrict__ cnt) {
    int e = blockIdx.x * blockDim.x + threadIdx.x;
    if (e < EDGESN) atomicAdd(&cnt[dst[e]], 1);
}
__global__ void scan1_kernel(const int* __restrict__ cnt, int* __restrict__ rowptr,
                             int* __restrict__ bsum) {
    __shared__ int tmp[1024];
    int t = threadIdx.x;
    int i = blockIdx.x * 1024 + t;
    int v = (i < NODESN) ? cnt[i] : 0;
    tmp[t] = v;
    __syncthreads();
    for (int off = 1; off < 1024; off <<= 1) {
        int add = (t >= off) ? tmp[t - off] : 0;
        __syncthreads();
        tmp[t] += add;
        __syncthreads();
    }
    if (i < NODESN) rowptr[i + 1] = tmp[t];
    if (t == 1023) bsum[blockIdx.x] = tmp[1023];
}
__global__ void scan2_kernel(int* __restrict__ bsum, int nb) {
    if (threadIdx.x == 0) {
        int run = 0;
        for (int b = 0; b < nb; b++) { int s = bsum[b]; bsum[b] = run; run += s; }
    }
}
__global__ void scan3_kernel(const int* __restrict__ cnt, int* __restrict__ rowptr,
                             int* __restrict__ cursor, const int* __restrict__ bsum) {
    int i = blockIdx.x * 1024 + threadIdx.x;
    if (i < NODESN) {
        int incl = rowptr[i + 1] + bsum[blockIdx.x];
        rowptr[i + 1] = incl;
        cursor[i] = incl - cnt[i];
    }
    if (i == 0) rowptr[0] = 0;
}
__global__ void scatter_kernel(const int* __restrict__ dst, const int* __restrict__ src,
                               int* __restrict__ cursor, int* __restrict__ perm,
                               int* __restrict__ srcp) {
    int e = blockIdx.x * blockDim.x + threadIdx.x;
    if (e >= EDGESN) return;
    int pos = atomicAdd(&cursor[dst[e]], 1);
    perm[pos] = e;
    srcp[pos] = src[e];
}

// ---------------- node init ----------------
__global__ void init_nodes_kernel(const int* __restrict__ x, const float* __restrict__ embed_w,
                                  float* __restrict__ hA) {
    int idx = blockIdx.x * blockDim.x + threadIdx.x;
    if (idx >= NODESN * 72) return;
    int n = idx / 72, pos = idx - n * 72;
    hA[idx] = (pos < 8) ? embed_w[x[n] * 8 + pos] : 0.0f;
}

// ---------------- radial MLP with TF32 tensor-core second GEMM ----------------
// Processes CSR slots: slot p in [blockIdx*128, +128), edge id = perm[p].
// Output layout FRAGMENT-NATIVE indexed by slot p: per 128-slot block, per 16x8
// tile (mtile, nt): element (r, n=nt*8+nn): lane=(r&7)*4+(nn>>1), reg=(r>>3)*2+(nn&1)
__device__ __forceinline__ float to_tf32(float x) {
    uint32_t u;
    asm("cvt.rna.tf32.f32 %0, %1;" : "=r"(u) : "f"(x));
    return __uint_as_float(u);
}

#define HSTR 136   // 136 mod 32 == 8 -> A-fragment LDS conflict-free

// pack W2 (tf32-rounded) into B-fragment order:
// out[(kc*OD + n)*4 + qc] = { W2[(kc*8+qc)*OD+n], W2[(kc*8+qc+4)*OD+n] }
__global__ void pack_w2_kernel(const float* __restrict__ W2, float2* __restrict__ out, int OD) {
    int idx = blockIdx.x * blockDim.x + threadIdx.x;
    if (idx >= 8 * OD * 4) return;
    int kc = idx / (OD * 4);
    int rem = idx - kc * OD * 4;
    int n = rem >> 2, qc = rem & 3;
    out[idx] = make_float2(to_tf32(W2[(kc * 8 + qc) * OD + n]),
                           to_tf32(W2[(kc * 8 + qc + 4) * OD + n]));
}

// one pass: NT n-tiles starting at ntb; accumulators NT*4 regs
template<int OD, int NT>
__device__ __forceinline__ void mma_pass(const float* hidT, const float2* __restrict__ W2p,
                                         const float* B2s, float* woutb,
                                         int ntb, int m0, int warp, int lane) {
    constexpr int NTall = OD / 8;
    int qr = lane >> 2, qc = lane & 3;
    float c0[NT], c1[NT], c2[NT], c3[NT];
    #pragma unroll
    for (int n = 0; n < NT; n++) { c0[n]=0.f; c1[n]=0.f; c2[n]=0.f; c3[n]=0.f; }
    #pragma unroll
    for (int kc = 0; kc < 8; kc++) {
        int kA = kc * 8 + qc;
        uint32_t a0 = __float_as_uint(hidT[kA * HSTR + m0 + qr]);
        uint32_t a1 = __float_as_uint(hidT[kA * HSTR + m0 + qr + 8]);
        uint32_t a2 = __float_as_uint(hidT[(kA + 4) * HSTR + m0 + qr]);
        uint32_t a3 = __float_as_uint(hidT[(kA + 4) * HSTR + m0 + qr + 8]);
        #pragma unroll
        for (int nt = 0; nt < NT; nt++) {
            float2 bv = __ldg(&W2p[(kc * OD + (ntb + nt) * 8) * 4 + qr * 4 + qc]);
            uint32_t b0 = __float_as_uint(bv.x);
            uint32_t b1 = __float_as_uint(bv.y);
            asm volatile("mma.sync.aligned.m16n8k8.row.col.f32.tf32.tf32.f32 "
                         "{%0,%1,%2,%3}, {%4,%5,%6,%7}, {%8,%9}, {%0,%1,%2,%3};"
                         : "+f"(c0[nt]), "+f"(c1[nt]), "+f"(c2[nt]), "+f"(c3[nt])
                         : "r"(a0), "r"(a1), "r"(a2), "r"(a3), "r"(b0), "r"(b1));
        }
    }
    #pragma unroll
    for (int nt = 0; nt < NT; nt++) {
        int n0 = (ntb + nt) * 8 + qc * 2;
        float4 v = make_float4(c0[nt] + B2s[n0], c1[nt] + B2s[n0 + 1],
                               c2[nt] + B2s[n0], c3[nt] + B2s[n0 + 1]);
        *(float4*)&woutb[(size_t)(warp * NTall + ntb + nt) * 128 + lane * 4] = v;
    }
}

template<int OD>
__global__ void __launch_bounds__(256, 4) radial_tc_kernel(
                                 const float* __restrict__ ev, const int* __restrict__ perm,
                                 const float* __restrict__ W1, const float* __restrict__ B1,
                                 const float2* __restrict__ W2p, const float* __restrict__ B2,
                                 float* __restrict__ Wout) {
    extern __shared__ float sm[];
    float* W1s  = sm;                    // 16*64
    float* B1s  = W1s + 1024;            // 64
    float* B2s  = B1s + 64;              // OD
    float* hidT = B2s + OD;              // [64][HSTR] tf32-rounded
    int t = threadIdx.x;
    int p0 = blockIdx.x * 128;
    for (int i = t; i < 1024;   i += 256) W1s[i] = W1[i];
    for (int i = t; i < 64;     i += 256) B1s[i] = B1[i];
    for (int i = t; i < OD;     i += 256) B2s[i] = B2[i];
    __syncthreads();
    // hidden layer: soft-onehot has at most 2 active bins -> 2 FMAs per hidden unit
    {
        int p = t & 127;
        int hg = t >> 7;
        int eg = __ldg(&perm[p0 + p]);
        float x = __ldg(&ev[eg * 3]), y = __ldg(&ev[eg * 3 + 1]), z = __ldg(&ev[eg * 3 + 2]);
        float r = sqrtf(x*x + y*y + z*z + 1e-12f);
        float q = r * (17.0f / 3.0f);           // r/step, step = 3/17
        int ib = (int)floorf(q);
        float f0 = 0.0f, f1 = 0.0f;
        int r0 = 0, r1 = 0;
        {
            int b = ib;
            if (b >= 1 && b <= 16) {
                float d = q - (float)b;
                if (fabsf(d) < 1.0f) { f0 = 8.4335731f * __expf(-2.0f / (1.0f - d * d)); r0 = b - 1; }
            }
            b = ib + 1;
            if (b >= 1 && b <= 16) {
                float d = q - (float)b;
                if (fabsf(d) < 1.0f) { f1 = 8.4335731f * __expf(-2.0f / (1.0f - d * d)); r1 = b - 1; }
            }
        }
        const float* w1r0 = &W1s[r0 * 64];
        const float* w1r1 = &W1s[r1 * 64];
        #pragma unroll
        for (int j = 0; j < 32; j++) {
            int h = hg * 32 + j;
            float acc = B1s[h] + f0 * w1r0[h] + f1 * w1r1[h];
            acc = acc / (1.0f + __expf(-acc));
            hidT[h * HSTR + p] = to_tf32(acc);
        }
    }
    __syncthreads();
    // second GEMM 128 x OD x 64: warp -> 1 m-tile, two accumulator passes over n
    {
        constexpr int NTT = OD / 8;
        constexpr int NT0 = (NTT + 1) / 2;
        constexpr int NT1 = NTT - NT0;
        int warp = t >> 5, lane = t & 31;
        int m0 = warp * 16;
        float* woutb = Wout + (size_t)blockIdx.x * (128 * OD);
        mma_pass<OD, NT0>(hidT, W2p, B2s, woutb, 0,   m0, warp, lane);
        if (NT1 > 0)
            mma_pass<OD, NT1>(hidT, W2p, B2s, woutb, NT0, m0, warp, lane);
    }
}

// ---------------- tp_first: slot-ordered, linear m writes ----------------
__global__ void tp_first_kernel(const float* __restrict__ h, const int* __restrict__ perm,
                                const int* __restrict__ srcp, const float* __restrict__ ev,
                                const float* __restrict__ w, float* __restrict__ m) {
    int gid = blockIdx.x * blockDim.x + threadIdx.x;
    int pos = gid >> 3, c = gid & 7;
    if (pos >= EDGESN) return;
    int e = __ldg(&perm[pos]);
    int s = __ldg(&srcp[pos]);
    float x = __ldg(&ev[e*3]), y = __ldg(&ev[e*3+1]), z = __ldg(&ev[e*3+2]);
    float r = sqrtf(x*x + y*y + z*z + 1e-12f);
    float inv = 1.0f / r; x *= inv; y *= inv; z *= inv;
    const float c3 = 1.7320508076f, c15 = 3.8729833462f, c5 = 2.2360679775f;
    float sh1[3] = { c3*y, c3*z, c3*x };
    float sh2[5] = { c15*x*y, c15*y*z, 0.5f*c5*(3.0f*z*z-1.0f), c15*x*z, 0.5f*c15*(x*x-y*y) };
    float hs = h[s * 72 + c];
    int pL = pos & 127;
    int mtile = pL >> 4, rr = pL & 15;
    int lane = (rr & 7) * 4 + (c >> 1);
    int reg = ((rr >> 3) << 1) + (c & 1);
    const float* wb = &w[(size_t)(pos >> 7) * 3072 + (size_t)mtile * 384 + lane * 4 + reg];
    float w0 = wb[0], w1v = wb[128], w2v = wb[256];
    float* mp = &m[(size_t)pos * 72];
    mp[c] = w0 * hs;
    float hv = w1v * hs, ht = w2v * hs;
    #pragma unroll
    for (int i = 0; i < 3; i++) mp[8 + c*3 + i] = hv * sh1[i];
    #pragma unroll
    for (int j = 0; j < 5; j++) mp[32 + c*5 + j] = ht * sh2[j];
}

// ---------------- fused streaming gather + update A (float4 gather) ----------------
// 288 threads = 16 nodes x 18 float4-lanes; m row = 72 floats = 18 float4
__global__ void updateA_kernel(const float4* __restrict__ m4, const int* __restrict__ row_ptr,
                               const float* __restrict__ hin, const float* __restrict__ lin0,
                               float4* __restrict__ hout4) {
    int node = blockIdx.x * 16 + threadIdx.x / 18;
    int kk = threadIdx.x % 18;
    if (node >= NODESN) return;
    int beg = row_ptr[node], end = row_ptr[node + 1];
    float4 acc = make_float4(0.f, 0.f, 0.f, 0.f);
    #pragma unroll 2
    for (int j = beg; j < end; j++) {
        float4 v = m4[(size_t)j * 18 + kk];
        acc.x += v.x; acc.y += v.y; acc.z += v.z; acc.w += v.w;
    }
    float vv[4] = { acc.x * 0.25f, acc.y * 0.25f, acc.z * 0.25f, acc.w * 0.25f };
    if (kk < 2) {       // k = kk*4+comp in [0,8): lin0 + silu
        const float* hp = &hin[node * 72];
        #pragma unroll
        for (int comp = 0; comp < 4; comp++) {
            int k = kk * 4 + comp;
            float a2 = 0.0f;
            #pragma unroll
            for (int c = 0; c < 8; c++) a2 += hp[c] * lin0[c * 8 + k];
            float v = vv[comp] + a2 * 0.35355339059f;
            vv[comp] = v / (1.0f + __expf(-v));
        }
    }
    hout4[(size_t)node * 18 + kk] = make_float4(vv[0], vv[1], vv[2], vv[3]);
}

// ---------------- tp_uuu: slot-ordered, linear hb/w access ----------------
__global__ void tp_uuu_kernel(const float* __restrict__ h, const int* __restrict__ srcp,
                              const float* __restrict__ w, float* __restrict__ hb) {
    __shared__ float CGs[15 * 125];
    for (int i = threadIdx.x; i < 1875; i += 256) CGs[i] = g_CG[i];
    __syncthreads();
    int gid = blockIdx.x * 256 + threadIdx.x;
    int pos = gid >> 3, c = gid & 7;
    if (pos >= EDGESN) return;
    int s = __ldg(&srcp[pos]);
    const float* hp = &h[s * 72];
    float A0[1], A1[3], A2[5], B0[1], B1[3], B2[5];
    A0[0] = hp[c];
    #pragma unroll
    for (int i = 0; i < 3; i++) A1[i] = hp[8 + c*3 + i];
    #pragma unroll
    for (int j = 0; j < 5; j++) A2[j] = hp[32 + c*5 + j];
    float* bp = &hb[(size_t)pos * 72];
    float b0raw = bp[c];
    B0[0] = b0raw / (1.0f + __expf(-b0raw));   // act() applied on consume
    #pragma unroll
    for (int i = 0; i < 3; i++) B1[i] = bp[8 + c*3 + i];
    #pragma unroll
    for (int j = 0; j < 5; j++) B2[j] = bp[32 + c*5 + j];
    // fragment-native w read (slot-indexed)
    float wp[15];
    {
        int pL = pos & 127;
        int mtile = pL >> 4, rr = pL & 15;
        int lane = (rr & 7) * 4 + (c >> 1);
        int reg = ((rr >> 3) << 1) + (c & 1);
        const float* wb = &w[(size_t)(pos >> 7) * 15360 + (size_t)mtile * 1920 + lane * 4 + reg];
        #pragma unroll
        for (int p = 0; p < 15; p++) wp[p] = wb[p * 128];
    }
    float O0[1] = {0.f}, O1[3] = {0.f,0.f,0.f}, O2[5] = {0.f,0.f,0.f,0.f,0.f};

#define DOPATH(P, L1, L2, L3, AR, BR, OR, D1, D2, D3) { \
    const float* cg = &CGs[(P) * 125]; float wl = wp[P]; \
    _Pragma("unroll") for (int i = 0; i < (D1); i++) { float aw = AR[i] * wl; \
        _Pragma("unroll") for (int j = 0; j < (D2); j++) { float ab = aw * BR[j]; \
            _Pragma("unroll") for (int k = 0; k < (D3); k++) { \
                if (cg_ok(L1,L2,L3,i,j,k)) OR[k] += ab * cg[i*25 + j*5 + k]; } } } }

    DOPATH(0,  0,0,0, A0, B0, O0, 1, 1, 1)
    DOPATH(1,  0,1,1, A0, B1, O1, 1, 3, 3)
    DOPATH(2,  0,2,2, A0, B2, O2, 1, 5, 5)
    DOPATH(3,  1,0,1, A1, B0, O1, 3, 1, 3)
    DOPATH(4,  1,1,0, A1, B1, O0, 3, 3, 1)
    DOPATH(5,  1,1,1, A1, B1, O1, 3, 3, 3)
    DOPATH(6,  1,1,2, A1, B1, O2, 3, 3, 5)
    DOPATH(7,  1,2,1, A1, B2, O1, 3, 5, 3)
    DOPATH(8,  1,2,2, A1, B2, O2, 3, 5, 5)
    DOPATH(9,  2,0,2, A2, B0, O2, 5, 1, 5)
    DOPATH(10, 2,1,1, A2, B1, O1, 5, 3, 3)
    DOPATH(11, 2,1,2, A2, B1, O2, 5, 3, 5)
    DOPATH(12, 2,2,0, A2, B2, O0, 5, 5, 1)
    DOPATH(13, 2,2,1, A2, B2, O1, 5, 5, 3)
    DOPATH(14, 2,2,2, A2, B2, O2, 5, 5, 5)
#undef DOPATH

    const float n0 = 0.57735026919f, n12 = 0.40824829046f;
    bp[c] = O0[0] * n0;
    #pragma unroll
    for (int i = 0; i < 3; i++) bp[8 + c*3 + i] = O1[i] * n12;
    #pragma unroll
    for (int j = 0; j < 5; j++) bp[32 + c*5 + j] = O2[j] * n12;
}

// ---------------- fused streaming gather + update B (float4 gather) ----------------
__global__ void updateB_kernel(const float4* __restrict__ m4, const int* __restrict__ row_ptr,
                               const float* __restrict__ hin, const float* __restrict__ lin,
                               float4* __restrict__ hout4) {
    int node = blockIdx.x * 16 + threadIdx.x / 18;
    int kk = threadIdx.x % 18;
    if (node >= NODESN) return;
    int beg = row_ptr[node], end = row_ptr[node + 1];
    float4 acc = make_float4(0.f, 0.f, 0.f, 0.f);
    #pragma unroll 2
    for (int j = beg; j < end; j++) {
        float4 v = m4[(size_t)j * 18 + kk];
        acc.x += v.x; acc.y += v.y; acc.z += v.z; acc.w += v.w;
    }
    float vv[4] = { acc.x * 0.25f, acc.y * 0.25f, acc.z * 0.25f, acc.w * 0.25f };
    const float* hp = &hin[node * 72];
    const float R8 = 0.35355339059f;
    #pragma unroll
    for (int comp = 0; comp < 4; comp++) {
        int k = kk * 4 + comp;
        float a2 = 0.0f;
        if (k < 8) {
            #pragma unroll
            for (int c = 0; c < 8; c++) a2 += hp[c] * lin[c * 8 + k];
            float v = vv[comp] + a2 * R8;
            vv[comp] = v / (1.0f + __expf(-v));
        } else if (k < 32) {
            int dd = (k - 8) / 3, i = (k - 8) % 3;
            #pragma unroll
            for (int c = 0; c < 8; c++) a2 += hp[8 + c*3 + i] * lin[64 + c * 8 + dd];
            vv[comp] += a2 * R8;
        } else {
            int dd = (k - 32) / 5, j2 = (k - 32) % 5;
            #pragma unroll
            for (int c = 0; c < 8; c++) a2 += hp[32 + c*5 + j2] * lin[128 + c * 8 + dd];
            vv[comp] += a2 * R8;
        }
    }
    hout4[(size_t)node * 18 + kk] = make_float4(vv[0], vv[1], vv[2], vv[3]);
}

// ---------------- readout ----------------
__global__ void readout_kernel(const float* __restrict__ h, const float* __restrict__ ow,
                               float* __restrict__ out) {
    __shared__ float W[1536];
    for (int i = threadIdx.x; i < 1536; i += 256) W[i] = ow[i];
    __syncthreads();
    int n = blockIdx.x * blockDim.x + threadIdx.x;
    if (n >= NODESN) return;
    const float* hp = &h[n * 72];
    float hs[72];
    #pragma unroll
    for (int i = 0; i < 72; i++) hs[i] = hp[i];
    float acc[8] = {0,0,0,0,0,0,0,0};
    const float i1n = 0.57735026919f, i2n = 0.44721359550f;
    #pragma unroll
    for (int i = 0; i < 8; i++) {
        #pragma unroll
        for (int j = 0; j < 8; j++) {
            float p0 = hs[i] * hs[j];
            float p1 = (hs[8+i*3]*hs[8+j*3] + hs[9+i*3]*hs[9+j*3] + hs[10+i*3]*hs[10+j*3]) * i1n;
            float p2 = 0.0f;
            #pragma unroll
            for (int q = 0; q < 5; q++) p2 += hs[32+i*5+q] * hs[32+j*5+q];
            p2 *= i2n;
            int base = (i * 8 + j) * 8;
            #pragma unroll
            for (int k = 0; k < 8; k++)
                acc[k] += p0 * W[base + k] + p1 * W[512 + base + k] + p2 * W[1024 + base + k];
        }
    }
    const float fn = 0.07216878365f;  // 1/sqrt(192)
    #pragma unroll
    for (int k = 0; k < 8; k++) out[n * 8 + k] = acc[k] * fn;
}

// ---------------- launch ----------------
extern "C" void kernel_launch(void* const* d_in, const int* in_sizes, int n_in,
                              void* d_out, int out_size) {
    const int*   x       = (const int*)d_in[0];
    const int*   ei      = (const int*)d_in[1];
    const float* ev      = (const float*)d_in[2];
    const float* embed_w = (const float*)d_in[3];
    const float* lin0    = (const float*)d_in[4];
    const float* lin1    = (const float*)d_in[5];
    const float* lin2    = (const float*)d_in[6];
    const float* out_w   = (const float*)d_in[7];
    const float* r0w1 = (const float*)d_in[8],  *r0b1 = (const float*)d_in[9];
    const float* r0w2 = (const float*)d_in[10], *r0b2 = (const float*)d_in[11];
    const float* r1w1 = (const float*)d_in[12], *r1b1 = (const float*)d_in[13];
    const float* r1w2 = (const float*)d_in[14], *r1b2 = (const float*)d_in[15];
    const float* r2w1 = (const float*)d_in[16], *r2b1 = (const float*)d_in[17];
    const float* r2w2 = (const float*)d_in[18], *r2b2 = (const float*)d_in[19];
    float* out = (float*)d_out;
    const int* src = ei;
    const int* dst = ei + EDGESN;

    float *hA, *hB, *hb, *w0, *w1, *w2;
    float2 *w2p0, *w2p1, *w2p2;
    int *cnt, *rowptr, *cursor, *perm, *srcp, *bsum;
    cudaGetSymbolAddress((void**)&hA, g_hA);
    cudaGetSymbolAddress((void**)&hB, g_hB);
    cudaGetSymbolAddress((void**)&hb, g_hb);
    cudaGetSymbolAddress((void**)&w0, g_w0);
    cudaGetSymbolAddress((void**)&w1, g_w1);
    cudaGetSymbolAddress((void**)&w2, g_w2);
    cudaGetSymbolAddress((void**)&w2p0, g_w2p0);
    cudaGetSymbolAddress((void**)&w2p1, g_w2p1);
    cudaGetSymbolAddress((void**)&w2p2, g_w2p2);
    cudaGetSymbolAddress((void**)&cnt, g_cnt);
    cudaGetSymbolAddress((void**)&rowptr, g_rowptr);
    cudaGetSymbolAddress((void**)&cursor, g_cursor);
    cudaGetSymbolAddress((void**)&perm, g_perm);
    cudaGetSymbolAddress((void**)&srcp, g_srcp);
    cudaGetSymbolAddress((void**)&bsum, g_bsum);

    size_t sh24  = (size_t)(1024 + 64 + 24 + 64*HSTR) * 4;    // 39264 B
    size_t sh120 = (size_t)(1024 + 64 + 120 + 64*HSTR) * 4;   // 39648 B
    cudaFuncSetAttribute(radial_tc_kernel<24>,  cudaFuncAttributeMaxDynamicSharedMemorySize, (int)sh24);
    cudaFuncSetAttribute(radial_tc_kernel<120>, cudaFuncAttributeMaxDynamicSharedMemorySize, (int)sh120);

    const int NB72 = (NODESN * 72 + 255) / 256;
    const int NGB  = (NODESN + 15) / 16;          // 2500 blocks, 288 thr, 16 nodes each
    const int NSCAN = (NODESN + 1023) / 1024;     // 40

    cg_init_kernel<<<15, 125>>>();
    hist_zero_kernel<<<(NODESN + 255) / 256, 256>>>(cnt);
    hist_kernel<<<(EDGESN + 255) / 256, 256>>>(dst, cnt);
    scan1_kernel<<<NSCAN, 1024>>>(cnt, rowptr, bsum);
    scan2_kernel<<<1, 32>>>(bsum, NSCAN);
    scan3_kernel<<<NSCAN, 1024>>>(cnt, rowptr, cursor, bsum);
    scatter_kernel<<<(EDGESN + 255) / 256, 256>>>(dst, src, cursor, perm, srcp);
    pack_w2_kernel<<<(8 * 120 * 4 + 255) / 256, 256>>>(r2w2, w2p2, 120);
    radial_tc_kernel<120><<<EDGESN / 128, 256, sh120>>>(ev, perm, r2w1, r2b1, w2p2, r2b2, w2);
    pack_w2_kernel<<<(8 * 24 * 4 + 255) / 256, 256>>>(r0w2, w2p0, 24);
    pack_w2_kernel<<<(8 * 120 * 4 + 255) / 256, 256>>>(r1w2, w2p1, 120);

    init_nodes_kernel<<<NB72, 256>>>(x, embed_w, hA);

    radial_tc_kernel<24><<<EDGESN / 128, 256, sh24>>>(ev, perm, r0w1, r0b1, w2p0, r0b2, w0);
    tp_first_kernel<<<EDGESN * 8 / 256, 256>>>(hA, perm, srcp, ev, w0, hb);
    updateA_kernel<<<NGB, 288>>>((const float4*)hb, rowptr, hA, lin0, (float4*)hB);

    radial_tc_kernel<120><<<EDGESN / 128, 256, sh120>>>(ev, perm, r1w1, r1b1, w2p1, r1b2, w1);
    tp_uuu_kernel<<<EDGESN * 8 / 256, 256>>>(hB, srcp, w1, hb);
    updateB_kernel<<<NGB, 288>>>((const float4*)hb, rowptr, hB, lin1, (float4*)hA);

    tp_uuu_kernel<<<EDGESN * 8 / 256, 256>>>(hA, srcp, w2, hb);
    updateB_kernel<<<NGB, 288>>>((const float4*)hb, rowptr, hA, lin2, (float4*)hB);

    readout_kernel<<<(NODESN + 255) / 256, 256>>>(hB, out_w, out);
}

// round 17
// speedup vs baseline: 1.1269x; 1.0104x over previous
#include <cuda_runtime.h>
#include <cuda_fp16.h>
#include <cuda_bf16.h>
#include <math.h>
#include <stdint.h>

#define NODESN 40000
#define EDGESN 640000

// ---------------- static device scratch ----------------
__device__ float g_CG[15 * 125];
__device__ float g_hA[NODESN * 72];
__device__ float g_hB[NODESN * 72];
__device__ float g_hb[EDGESN * 72];      // messages, CSR slot order (fp32)
__device__ __half g_w0[EDGESN * 24];     // radial outputs, CSR-pos fragment order, fp16
__device__ __half g_w1[EDGESN * 120];
__device__ __half g_w2[EDGESN * 120];
__device__ float2 g_w2p0[8 * 24 * 4];    // packed tf32 W2, layer0 (OD=24)
__device__ float2 g_w2p1[8 * 120 * 4];   // layer1
__device__ float2 g_w2p2[8 * 120 * 4];   // layer2
__device__ int   g_cnt[NODESN];
__device__ int   g_rowptr[NODESN + 1];
__device__ int   g_cursor[NODESN];
__device__ int   g_perm[EDGESN];         // perm[pos] = edge id
__device__ int   g_srcp[EDGESN];         // srcp[pos] = src[perm[pos]]
__device__ int   g_bsum[64];

// ---------------- CG init (values computed in fp64 on device) ----------------
__device__ double dfact(int n) {
    const double f[9] = {1.,1.,2.,6.,24.,120.,720.,5040.,40320.};
    return f[n];
}
__device__ double dclebsch(int j1,int m1,int j2,int m2,int j3,int m3) {
    if (m1 + m2 != m3) return 0.0;
    double pref = sqrt((2.0*j3+1.0)*dfact(j3+j1-j2)*dfact(j3-j1+j2)*dfact(j1+j2-j3)/dfact(j1+j2+j3+1));
    pref *= sqrt(dfact(j3+m3)*dfact(j3-m3)*dfact(j1-m1)*dfact(j1+m1)*dfact(j2-m2)*dfact(j2+m2));
    int lo = max(0, max(j2-j3-m1, j1-j3+m2));
    int hi = min(j1+j2-j3, min(j1-m1, j2+m2));
    double s = 0.0;
    for (int k = lo; k <= hi; k++) {
        double d = dfact(k)*dfact(j1+j2-j3-k)*dfact(j1-m1-k)*dfact(j2+m2-k)*dfact(j3-j2+m1+k)*dfact(j3-j1-m2+k);
        s += ((k & 1) ? -1.0 : 1.0) / d;
    }
    return pref * s;
}
__device__ void u_elem(int l, int row, int col, double* re, double* im) {
    int m = row - l;
    const double s2 = 0.7071067811865476;
    double r = 0.0, ii = 0.0;
    double sgn = (m & 1) ? -1.0 : 1.0;
    if (m > 0) {
        if (col == m + l) r = sgn * s2;
        else if (col == l - m) r = s2;
    } else if (m == 0) {
        if (col == l) r = 1.0;
    } else {
        if (col == m + l) ii = s2;
        else if (col == l - m) ii = -sgn * s2;
    }
    *re = r; *im = ii;
}
__constant__ int c_P[15][3] = {{0,0,0},{0,1,1},{0,2,2},{1,0,1},{1,1,0},{1,1,1},{1,1,2},
                               {1,2,1},{1,2,2},{2,0,2},{2,1,1},{2,1,2},{2,2,0},{2,2,1},{2,2,2}};

__global__ void cg_init_kernel() {
    int p = blockIdx.x;
    int l1 = c_P[p][0], l2 = c_P[p][1], l3 = c_P[p][2];
    int d1 = 2*l1+1, d2 = 2*l2+1, d3 = 2*l3+1;
    int t = threadIdx.x;                 // 0..124
    int a = t / 25, b = (t / 5) % 5, c = t % 5;
    double tre = 0.0, tim = 0.0;
    bool inr = (a < d1 && b < d2 && c < d3);
    if (inr) {
        for (int m = 0; m < d1; m++) {
            double u1r, u1i; u_elem(l1, a, m, &u1r, &u1i); u1i = -u1i;
            if (u1r == 0.0 && u1i == 0.0) continue;
            for (int n = 0; n < d2; n++) {
                double u2r, u2i; u_elem(l2, b, n, &u2r, &u2i); u2i = -u2i;
                if (u2r == 0.0 && u2i == 0.0) continue;
                int m3 = (m - l1) + (n - l2);
                if (m3 < -l3 || m3 > l3) continue;
                int o = m3 + l3;
                double u3r, u3i; u_elem(l3, c, o, &u3r, &u3i);
                if (u3r == 0.0 && u3i == 0.0) continue;
                double cv = dclebsch(l1, m-l1, l2, n-l2, l3, m3);
                if (cv == 0.0) continue;
                double pr = u1r*u2r - u1i*u2i;
                double pi = u1r*u2i + u1i*u2r;
                tre += (pr*u3r - pi*u3i) * cv;
                tim += (pr*u3i + pi*u3r) * cv;
            }
        }
    }
    __shared__ double sre[125], sim[125];
    __shared__ int useim;
    sre[t] = fabs(tre); sim[t] = fabs(tim);
    __syncthreads();
    if (t == 0) {
        double mr = 0.0, mi = 0.0;
        for (int q = 0; q < 125; q++) { mr = fmax(mr, sre[q]); mi = fmax(mi, sim[q]); }
        useim = (mi > mr) ? 1 : 0;
    }
    __syncthreads();
    g_CG[p * 125 + t] = inr ? (float)(useim ? tim : tre) : 0.0f;
}

// compile-time superset of real-CG sparsity (values still from g_CG, so superset is safe)
__host__ __device__ constexpr bool cg_ok(int l1,int l2,int l3,int i,int j,int k){
    int m1=i-l1, m2=j-l2, m3=k-l3;
    int a1=m1<0?-m1:m1, a2=m2<0?-m2:m2, a3=m3<0?-m3:m3;
    int s=a1+a2, d=(a1>a2)?(a1-a2):(a2-a1);
    if (a3!=s && a3!=d) return false;
    int neg=(m1<0)+(m2<0)+(m3<0);
    return ((neg&1)==((l1+l2+l3)&1));
}

// ---------------- CSR build ----------------
__global__ void hist_zero_kernel(int* __restrict__ cnt) {
    int i = blockIdx.x * blockDim.x + threadIdx.x;
    if (i < NODESN) cnt[i] = 0;
}
__global__ void hist_kernel(const int* __restrict__ dst, int* __restrict__ cnt) {
    int e = blockIdx.x * blockDim.x + threadIdx.x;
    if (e < EDGESN) atomicAdd(&cnt[dst[e]], 1);
}
__global__ void scan1_kernel(const int* __restrict__ cnt, int* __restrict__ rowptr,
                             int* __restrict__ bsum) {
    __shared__ int tmp[1024];
    int t = threadIdx.x;
    int i = blockIdx.x * 1024 + t;
    int v = (i < NODESN) ? cnt[i] : 0;
    tmp[t] = v;
    __syncthreads();
    for (int off = 1; off < 1024; off <<= 1) {
        int add = (t >= off) ? tmp[t - off] : 0;
        __syncthreads();
        tmp[t] += add;
        __syncthreads();
    }
    if (i < NODESN) rowptr[i + 1] = tmp[t];
    if (t == 1023) bsum[blockIdx.x] = tmp[1023];
}
__global__ void scan2_kernel(int* __restrict__ bsum, int nb) {
    if (threadIdx.x == 0) {
        int run = 0;
        for (int b = 0; b < nb; b++) { int s = bsum[b]; bsum[b] = run; run += s; }
    }
}
__global__ void scan3_kernel(const int* __restrict__ cnt, int* __restrict__ rowptr,
                             int* __restrict__ cursor, const int* __restrict__ bsum) {
    int i = blockIdx.x * 1024 + threadIdx.x;
    if (i < NODESN) {
        int incl = rowptr[i + 1] + bsum[blockIdx.x];
        rowptr[i + 1] = incl;
        cursor[i] = incl - cnt[i];
    }
    if (i == 0) rowptr[0] = 0;
}
__global__ void scatter_kernel(const int* __restrict__ dst, const int* __restrict__ src,
                               int* __restrict__ cursor, int* __restrict__ perm,
                               int* __restrict__ srcp) {
    int e = blockIdx.x * blockDim.x + threadIdx.x;
    if (e >= EDGESN) return;
    int pos = atomicAdd(&cursor[dst[e]], 1);
    perm[pos] = e;
    srcp[pos] = src[e];
}

// ---------------- node init ----------------
__global__ void init_nodes_kernel(const int* __restrict__ x, const float* __restrict__ embed_w,
                                  float* __restrict__ hA) {
    int idx = blockIdx.x * blockDim.x + threadIdx.x;
    if (idx >= NODESN * 72) return;
    int n = idx / 72, pos = idx - n * 72;
    hA[idx] = (pos < 8) ? embed_w[x[n] * 8 + pos] : 0.0f;
}

// ---------------- radial MLP with TF32 tensor-core second GEMM ----------------
// Processes CSR slots: slot p in [blockIdx*128, +128), edge id = perm[p].
// Output FRAGMENT-NATIVE (fp16) indexed by slot p: per 128-slot block, per 16x8
// tile (mtile, nt), 128 halfs: element (r, n=nt*8+nn): lane=(r&7)*4+(nn>>1),
// reg=(r>>3)*2+(nn&1); each lane stores its 4 regs as one 8-byte uint2.
__device__ __forceinline__ float to_tf32(float x) {
    uint32_t u;
    asm("cvt.rna.tf32.f32 %0, %1;" : "=r"(u) : "f"(x));
    return __uint_as_float(u);
}

#define HSTR 136   // 136 mod 32 == 8 -> A-fragment LDS conflict-free

// pack W2 (tf32-rounded) into B-fragment order:
// out[(kc*OD + n)*4 + qc] = { W2[(kc*8+qc)*OD+n], W2[(kc*8+qc+4)*OD+n] }
__global__ void pack_w2_kernel(const float* __restrict__ W2, float2* __restrict__ out, int OD) {
    int idx = blockIdx.x * blockDim.x + threadIdx.x;
    if (idx >= 8 * OD * 4) return;
    int kc = idx / (OD * 4);
    int rem = idx - kc * OD * 4;
    int n = rem >> 2, qc = rem & 3;
    out[idx] = make_float2(to_tf32(W2[(kc * 8 + qc) * OD + n]),
                           to_tf32(W2[(kc * 8 + qc + 4) * OD + n]));
}

// one pass: NT n-tiles starting at ntb; accumulators NT*4 regs
template<int OD, int NT>
__device__ __forceinline__ void mma_pass(const float* hidT, const float2* __restrict__ W2p,
                                         const float* B2s, __half* woutb,
                                         int ntb, int m0, int warp, int lane) {
    constexpr int NTall = OD / 8;
    int qr = lane >> 2, qc = lane & 3;
    float c0[NT], c1[NT], c2[NT], c3[NT];
    #pragma unroll
    for (int n = 0; n < NT; n++) { c0[n]=0.f; c1[n]=0.f; c2[n]=0.f; c3[n]=0.f; }
    #pragma unroll
    for (int kc = 0; kc < 8; kc++) {
        int kA = kc * 8 + qc;
        uint32_t a0 = __float_as_uint(hidT[kA * HSTR + m0 + qr]);
        uint32_t a1 = __float_as_uint(hidT[kA * HSTR + m0 + qr + 8]);
        uint32_t a2 = __float_as_uint(hidT[(kA + 4) * HSTR + m0 + qr]);
        uint32_t a3 = __float_as_uint(hidT[(kA + 4) * HSTR + m0 + qr + 8]);
        #pragma unroll
        for (int nt = 0; nt < NT; nt++) {
            float2 bv = __ldg(&W2p[(kc * OD + (ntb + nt) * 8) * 4 + qr * 4 + qc]);
            uint32_t b0 = __float_as_uint(bv.x);
            uint32_t b1 = __float_as_uint(bv.y);
            asm volatile("mma.sync.aligned.m16n8k8.row.col.f32.tf32.tf32.f32 "
                         "{%0,%1,%2,%3}, {%4,%5,%6,%7}, {%8,%9}, {%0,%1,%2,%3};"
                         : "+f"(c0[nt]), "+f"(c1[nt]), "+f"(c2[nt]), "+f"(c3[nt])
                         : "r"(a0), "r"(a1), "r"(a2), "r"(a3), "r"(b0), "r"(b1));
        }
    }
    #pragma unroll
    for (int nt = 0; nt < NT; nt++) {
        int n0 = (ntb + nt) * 8 + qc * 2;
        __half2 h01 = __floats2half2_rn(c0[nt] + B2s[n0], c1[nt] + B2s[n0 + 1]);
        __half2 h23 = __floats2half2_rn(c2[nt] + B2s[n0], c3[nt] + B2s[n0 + 1]);
        uint2 pk;
        pk.x = *(uint32_t*)&h01;
        pk.y = *(uint32_t*)&h23;
        *(uint2*)&woutb[(size_t)(warp * NTall + ntb + nt) * 128 + lane * 4] = pk;
    }
}

template<int OD>
__global__ void __launch_bounds__(256, 4) radial_tc_kernel(
                                 const float* __restrict__ ev, const int* __restrict__ perm,
                                 const float* __restrict__ W1, const float* __restrict__ B1,
                                 const float2* __restrict__ W2p, const float* __restrict__ B2,
                                 __half* __restrict__ Wout) {
    extern __shared__ float sm[];
    float* W1s  = sm;                    // 16*64
    float* B1s  = W1s + 1024;            // 64
    float* B2s  = B1s + 64;              // OD
    float* hidT = B2s + OD;              // [64][HSTR] tf32-rounded
    int t = threadIdx.x;
    int p0 = blockIdx.x * 128;
    for (int i = t; i < 1024;   i += 256) W1s[i] = W1[i];
    for (int i = t; i < 64;     i += 256) B1s[i] = B1[i];
    for (int i = t; i < OD;     i += 256) B2s[i] = B2[i];
    __syncthreads();
    // hidden layer: soft-onehot has at most 2 active bins -> 2 FMAs per hidden unit
    {
        int p = t & 127;
        int hg = t >> 7;
        int eg = __ldg(&perm[p0 + p]);
        float x = __ldg(&ev[eg * 3]), y = __ldg(&ev[eg * 3 + 1]), z = __ldg(&ev[eg * 3 + 2]);
        float r = sqrtf(x*x + y*y + z*z + 1e-12f);
        float q = r * (17.0f / 3.0f);           // r/step, step = 3/17
        int ib = (int)floorf(q);
        float f0 = 0.0f, f1 = 0.0f;
        int r0 = 0, r1 = 0;
        {
            int b = ib;
            if (b >= 1 && b <= 16) {
                float d = q - (float)b;
                if (fabsf(d) < 1.0f) { f0 = 8.4335731f * __expf(-2.0f / (1.0f - d * d)); r0 = b - 1; }
            }
            b = ib + 1;
            if (b >= 1 && b <= 16) {
                float d = q - (float)b;
                if (fabsf(d) < 1.0f) { f1 = 8.4335731f * __expf(-2.0f / (1.0f - d * d)); r1 = b - 1; }
            }
        }
        const float* w1r0 = &W1s[r0 * 64];
        const float* w1r1 = &W1s[r1 * 64];
        #pragma unroll
        for (int j = 0; j < 32; j++) {
            int h = hg * 32 + j;
            float acc = B1s[h] + f0 * w1r0[h] + f1 * w1r1[h];
            acc = acc / (1.0f + __expf(-acc));
            hidT[h * HSTR + p] = to_tf32(acc);
        }
    }
    __syncthreads();
    // second GEMM 128 x OD x 64: warp -> 1 m-tile, two accumulator passes over n
    {
        constexpr int NTT = OD / 8;
        constexpr int NT0 = (NTT + 1) / 2;
        constexpr int NT1 = NTT - NT0;
        int warp = t >> 5, lane = t & 31;
        int m0 = warp * 16;
        __half* woutb = Wout + (size_t)blockIdx.x * (128 * OD);
        mma_pass<OD, NT0>(hidT, W2p, B2s, woutb, 0,   m0, warp, lane);
        if (NT1 > 0)
            mma_pass<OD, NT1>(hidT, W2p, B2s, woutb, NT0, m0, warp, lane);
    }
}

// ---------------- tp_first: slot-ordered, linear m writes ----------------
__global__ void tp_first_kernel(const float* __restrict__ h, const int* __restrict__ perm,
                                const int* __restrict__ srcp, const float* __restrict__ ev,
                                const __half* __restrict__ w, float* __restrict__ m) {
    int gid = blockIdx.x * blockDim.x + threadIdx.x;
    int pos = gid >> 3, c = gid & 7;
    if (pos >= EDGESN) return;
    int e = __ldg(&perm[pos]);
    int s = __ldg(&srcp[pos]);
    float x = __ldg(&ev[e*3]), y = __ldg(&ev[e*3+1]), z = __ldg(&ev[e*3+2]);
    float r = sqrtf(x*x + y*y + z*z + 1e-12f);
    float inv = 1.0f / r; x *= inv; y *= inv; z *= inv;
    const float c3 = 1.7320508076f, c15 = 3.8729833462f, c5 = 2.2360679775f;
    float sh1[3] = { c3*y, c3*z, c3*x };
    float sh2[5] = { c15*x*y, c15*y*z, 0.5f*c5*(3.0f*z*z-1.0f), c15*x*z, 0.5f*c15*(x*x-y*y) };
    float hs = h[s * 72 + c];
    int pL = pos & 127;
    int mtile = pL >> 4, rr = pL & 15;
    int lane = (rr & 7) * 4 + (c >> 1);
    int reg = ((rr >> 3) << 1) + (c & 1);
    const __half* wb = &w[(size_t)(pos >> 7) * 3072 + (size_t)mtile * 384 + lane * 4 + reg];
    float w0 = __half2float(wb[0]);
    float w1v = __half2float(wb[128]);
    float w2v = __half2float(wb[256]);
    float* mp = &m[(size_t)pos * 72];
    mp[c] = w0 * hs;
    float hv = w1v * hs, ht = w2v * hs;
    #pragma unroll
    for (int i = 0; i < 3; i++) mp[8 + c*3 + i] = hv * sh1[i];
    #pragma unroll
    for (int j = 0; j < 5; j++) mp[32 + c*5 + j] = ht * sh2[j];
}

// ---------------- fused streaming gather + update A (float4 gather) ----------------
// 288 threads = 16 nodes x 18 float4-lanes; m row = 72 floats = 18 float4
__global__ void updateA_kernel(const float4* __restrict__ m4, const int* __restrict__ row_ptr,
                               const float* __restrict__ hin, const float* __restrict__ lin0,
                               float4* __restrict__ hout4) {
    int node = blockIdx.x * 16 + threadIdx.x / 18;
    int kk = threadIdx.x % 18;
    if (node >= NODESN) return;
    int beg = row_ptr[node], end = row_ptr[node + 1];
    float4 acc = make_float4(0.f, 0.f, 0.f, 0.f);
    #pragma unroll 2
    for (int j = beg; j < end; j++) {
        float4 v = m4[(size_t)j * 18 + kk];
        acc.x += v.x; acc.y += v.y; acc.z += v.z; acc.w += v.w;
    }
    float vv[4] = { acc.x * 0.25f, acc.y * 0.25f, acc.z * 0.25f, acc.w * 0.25f };
    if (kk < 2) {       // k = kk*4+comp in [0,8): lin0 + silu
        const float* hp = &hin[node * 72];
        #pragma unroll
        for (int comp = 0; comp < 4; comp++) {
            int k = kk * 4 + comp;
            float a2 = 0.0f;
            #pragma unroll
            for (int c = 0; c < 8; c++) a2 += hp[c] * lin0[c * 8 + k];
            float v = vv[comp] + a2 * 0.35355339059f;
            vv[comp] = v / (1.0f + __expf(-v));
        }
    }
    hout4[(size_t)node * 18 + kk] = make_float4(vv[0], vv[1], vv[2], vv[3]);
}

// ---------------- tp_uuu: slot-ordered, linear hb/w access ----------------
__global__ void tp_uuu_kernel(const float* __restrict__ h, const int* __restrict__ srcp,
                              const __half* __restrict__ w, float* __restrict__ hb) {
    __shared__ float CGs[15 * 125];
    for (int i = threadIdx.x; i < 1875; i += 256) CGs[i] = g_CG[i];
    __syncthreads();
    int gid = blockIdx.x * 256 + threadIdx.x;
    int pos = gid >> 3, c = gid & 7;
    if (pos >= EDGESN) return;
    int s = __ldg(&srcp[pos]);
    const float* hp = &h[s * 72];
    float A0[1], A1[3], A2[5], B0[1], B1[3], B2[5];
    A0[0] = hp[c];
    #pragma unroll
    for (int i = 0; i < 3; i++) A1[i] = hp[8 + c*3 + i];
    #pragma unroll
    for (int j = 0; j < 5; j++) A2[j] = hp[32 + c*5 + j];
    float* bp = &hb[(size_t)pos * 72];
    float b0raw = bp[c];
    B0[0] = b0raw / (1.0f + __expf(-b0raw));   // act() applied on consume
    #pragma unroll
    for (int i = 0; i < 3; i++) B1[i] = bp[8 + c*3 + i];
    #pragma unroll
    for (int j = 0; j < 5; j++) B2[j] = bp[32 + c*5 + j];
    // fragment-native w read (slot-indexed, fp16)
    float wp[15];
    {
        int pL = pos & 127;
        int mtile = pL >> 4, rr = pL & 15;
        int lane = (rr & 7) * 4 + (c >> 1);
        int reg = ((rr >> 3) << 1) + (c & 1);
        const __half* wb = &w[(size_t)(pos >> 7) * 15360 + (size_t)mtile * 1920 + lane * 4 + reg];
        #pragma unroll
        for (int p = 0; p < 15; p++) wp[p] = __half2float(wb[p * 128]);
    }
    float O0[1] = {0.f}, O1[3] = {0.f,0.f,0.f}, O2[5] = {0.f,0.f,0.f,0.f,0.f};

#define DOPATH(P, L1, L2, L3, AR, BR, OR, D1, D2, D3) { \
    const float* cg = &CGs[(P) * 125]; float wl = wp[P]; \
    _Pragma("unroll") for (int i = 0; i < (D1); i++) { float aw = AR[i] * wl; \
        _Pragma("unroll") for (int j = 0; j < (D2); j++) { float ab = aw * BR[j]; \
            _Pragma("unroll") for (int k = 0; k < (D3); k++) { \
                if (cg_ok(L1,L2,L3,i,j,k)) OR[k] += ab * cg[i*25 + j*5 + k]; } } } }

    DOPATH(0,  0,0,0, A0, B0, O0, 1, 1, 1)
    DOPATH(1,  0,1,1, A0, B1, O1, 1, 3, 3)
    DOPATH(2,  0,2,2, A0, B2, O2, 1, 5, 5)
    DOPATH(3,  1,0,1, A1, B0, O1, 3, 1, 3)
    DOPATH(4,  1,1,0, A1, B1, O0, 3, 3, 1)
    DOPATH(5,  1,1,1, A1, B1, O1, 3, 3, 3)
    DOPATH(6,  1,1,2, A1, B1, O2, 3, 3, 5)
    DOPATH(7,  1,2,1, A1, B2, O1, 3, 5, 3)
    DOPATH(8,  1,2,2, A1, B2, O2, 3, 5, 5)
    DOPATH(9,  2,0,2, A2, B0, O2, 5, 1, 5)
    DOPATH(10, 2,1,1, A2, B1, O1, 5, 3, 3)
    DOPATH(11, 2,1,2, A2, B1, O2, 5, 3, 5)
    DOPATH(12, 2,2,0, A2, B2, O0, 5, 5, 1)
    DOPATH(13, 2,2,1, A2, B2, O1, 5, 5, 3)
    DOPATH(14, 2,2,2, A2, B2, O2, 5, 5, 5)
#undef DOPATH

    const float n0 = 0.57735026919f, n12 = 0.40824829046f;
    bp[c] = O0[0] * n0;
    #pragma unroll
    for (int i = 0; i < 3; i++) bp[8 + c*3 + i] = O1[i] * n12;
    #pragma unroll
    for (int j = 0; j < 5; j++) bp[32 + c*5 + j] = O2[j] * n12;
}

// ---------------- fused streaming gather + update B (float4 gather) ----------------
__global__ void updateB_kernel(const float4* __restrict__ m4, const int* __restrict__ row_ptr,
                               const float* __restrict__ hin, const float* __restrict__ lin,
                               float4* __restrict__ hout4) {
    int node = blockIdx.x * 16 + threadIdx.x / 18;
    int kk = threadIdx.x % 18;
    if (node >= NODESN) return;
    int beg = row_ptr[node], end = row_ptr[node + 1];
    float4 acc = make_float4(0.f, 0.f, 0.f, 0.f);
    #pragma unroll 2
    for (int j = beg; j < end; j++) {
        float4 v = m4[(size_t)j * 18 + kk];
        acc.x += v.x; acc.y += v.y; acc.z += v.z; acc.w += v.w;
    }
    float vv[4] = { acc.x * 0.25f, acc.y * 0.25f, acc.z * 0.25f, acc.w * 0.25f };
    const float* hp = &hin[node * 72];
    const float R8 = 0.35355339059f;
    #pragma unroll
    for (int comp = 0; comp < 4; comp++) {
        int k = kk * 4 + comp;
        float a2 = 0.0f;
        if (k < 8) {
            #pragma unroll
            for (int c = 0; c < 8; c++) a2 += hp[c] * lin[c * 8 + k];
            float v = vv[comp] + a2 * R8;
            vv[comp] = v / (1.0f + __expf(-v));
        } else if (k < 32) {
            int dd = (k - 8) / 3, i = (k - 8) % 3;
            #pragma unroll
            for (int c = 0; c < 8; c++) a2 += hp[8 + c*3 + i] * lin[64 + c * 8 + dd];
            vv[comp] += a2 * R8;
        } else {
            int dd = (k - 32) / 5, j2 = (k - 32) % 5;
            #pragma unroll
            for (int c = 0; c < 8; c++) a2 += hp[32 + c*5 + j2] * lin[128 + c * 8 + dd];
            vv[comp] += a2 * R8;
        }
    }
    hout4[(size_t)node * 18 + kk] = make_float4(vv[0], vv[1], vv[2], vv[3]);
}

// ---------------- readout ----------------
__global__ void readout_kernel(const float* __restrict__ h, const float* __restrict__ ow,
                               float* __restrict__ out) {
    __shared__ float W[1536];
    for (int i = threadIdx.x; i < 1536; i += 256) W[i] = ow[i];
    __syncthreads();
    int n = blockIdx.x * blockDim.x + threadIdx.x;
    if (n >= NODESN) return;
    const float* hp = &h[n * 72];
    float hs[72];
    #pragma unroll
    for (int i = 0; i < 72; i++) hs[i] = hp[i];
    float acc[8] = {0,0,0,0,0,0,0,0};
    const float i1n = 0.57735026919f, i2n = 0.44721359550f;
    #pragma unroll
    for (int i = 0; i < 8; i++) {
        #pragma unroll
        for (int j = 0; j < 8; j++) {
            float p0 = hs[i] * hs[j];
            float p1 = (hs[8+i*3]*hs[8+j*3] + hs[9+i*3]*hs[9+j*3] + hs[10+i*3]*hs[10+j*3]) * i1n;
            float p2 = 0.0f;
            #pragma unroll
            for (int q = 0; q < 5; q++) p2 += hs[32+i*5+q] * hs[32+j*5+q];
            p2 *= i2n;
            int base = (i * 8 + j) * 8;
            #pragma unroll
            for (int k = 0; k < 8; k++)
                acc[k] += p0 * W[base + k] + p1 * W[512 + base + k] + p2 * W[1024 + base + k];
        }
    }
    const float fn = 0.07216878365f;  // 1/sqrt(192)
    #pragma unroll
    for (int k = 0; k < 8; k++) out[n * 8 + k] = acc[k] * fn;
}

// ---------------- launch ----------------
extern "C" void kernel_launch(void* const* d_in, const int* in_sizes, int n_in,
                              void* d_out, int out_size) {
    const int*   x       = (const int*)d_in[0];
    const int*   ei      = (const int*)d_in[1];
    const float* ev      = (const float*)d_in[2];
    const float* embed_w = (const float*)d_in[3];
    const float* lin0    = (const float*)d_in[4];
    const float* lin1    = (const float*)d_in[5];
    const float* lin2    = (const float*)d_in[6];
    const float* out_w   = (const float*)d_in[7];
    const float* r0w1 = (const float*)d_in[8],  *r0b1 = (const float*)d_in[9];
    const float* r0w2 = (const float*)d_in[10], *r0b2 = (const float*)d_in[11];
    const float* r1w1 = (const float*)d_in[12], *r1b1 = (const float*)d_in[13];
    const float* r1w2 = (const float*)d_in[14], *r1b2 = (const float*)d_in[15];
    const float* r2w1 = (const float*)d_in[16], *r2b1 = (const float*)d_in[17];
    const float* r2w2 = (const float*)d_in[18], *r2b2 = (const float*)d_in[19];
    float* out = (float*)d_out;
    const int* src = ei;
    const int* dst = ei + EDGESN;

    float *hA, *hB, *hb;
    __half *w0, *w1, *w2;
    float2 *w2p0, *w2p1, *w2p2;
    int *cnt, *rowptr, *cursor, *perm, *srcp, *bsum;
    cudaGetSymbolAddress((void**)&hA, g_hA);
    cudaGetSymbolAddress((void**)&hB, g_hB);
    cudaGetSymbolAddress((void**)&hb, g_hb);
    cudaGetSymbolAddress((void**)&w0, g_w0);
    cudaGetSymbolAddress((void**)&w1, g_w1);
    cudaGetSymbolAddress((void**)&w2, g_w2);
    cudaGetSymbolAddress((void**)&w2p0, g_w2p0);
    cudaGetSymbolAddress((void**)&w2p1, g_w2p1);
    cudaGetSymbolAddress((void**)&w2p2, g_w2p2);
    cudaGetSymbolAddress((void**)&cnt, g_cnt);
    cudaGetSymbolAddress((void**)&rowptr, g_rowptr);
    cudaGetSymbolAddress((void**)&cursor, g_cursor);
    cudaGetSymbolAddress((void**)&perm, g_perm);
    cudaGetSymbolAddress((void**)&srcp, g_srcp);
    cudaGetSymbolAddress((void**)&bsum, g_bsum);

    size_t sh24  = (size_t)(1024 + 64 + 24 + 64*HSTR) * 4;    // 39264 B
    size_t sh120 = (size_t)(1024 + 64 + 120 + 64*HSTR) * 4;   // 39648 B
    cudaFuncSetAttribute(radial_tc_kernel<24>,  cudaFuncAttributeMaxDynamicSharedMemorySize, (int)sh24);
    cudaFuncSetAttribute(radial_tc_kernel<120>, cudaFuncAttributeMaxDynamicSharedMemorySize, (int)sh120);

    const int NB72 = (NODESN * 72 + 255) / 256;
    const int NGB  = (NODESN + 15) / 16;          // 2500 blocks, 288 thr, 16 nodes each
    const int NSCAN = (NODESN + 1023) / 1024;     // 40

    cg_init_kernel<<<15, 125>>>();
    hist_zero_kernel<<<(NODESN + 255) / 256, 256>>>(cnt);
    hist_kernel<<<(EDGESN + 255) / 256, 256>>>(dst, cnt);
    scan1_kernel<<<NSCAN, 1024>>>(cnt, rowptr, bsum);
    scan2_kernel<<<1, 32>>>(bsum, NSCAN);
    scan3_kernel<<<NSCAN, 1024>>>(cnt, rowptr, cursor, bsum);
    scatter_kernel<<<(EDGESN + 255) / 256, 256>>>(dst, src, cursor, perm, srcp);
    pack_w2_kernel<<<(8 * 120 * 4 + 255) / 256, 256>>>(r2w2, w2p2, 120);
    radial_tc_kernel<120><<<EDGESN / 128, 256, sh120>>>(ev, perm, r2w1, r2b1, w2p2, r2b2, w2);
    pack_w2_kernel<<<(8 * 24 * 4 + 255) / 256, 256>>>(r0w2, w2p0, 24);
    pack_w2_kernel<<<(8 * 120 * 4 + 255) / 256, 256>>>(r1w2, w2p1, 120);

    init_nodes_kernel<<<NB72, 256>>>(x, embed_w, hA);

    radial_tc_kernel<24><<<EDGESN / 128, 256, sh24>>>(ev, perm, r0w1, r0b1, w2p0, r0b2, w0);
    tp_first_kernel<<<EDGESN * 8 / 256, 256>>>(hA, perm, srcp, ev, w0, hb);
    updateA_kernel<<<NGB, 288>>>((const float4*)hb, rowptr, hA, lin0, (float4*)hB);

    radial_tc_kernel<120><<<EDGESN / 128, 256, sh120>>>(ev, perm, r1w1, r1b1, w2p1, r1b2, w1);
    tp_uuu_kernel<<<EDGESN * 8 / 256, 256>>>(hB, srcp, w1, hb);
    updateB_kernel<<<NGB, 288>>>((const float4*)hb, rowptr, hB, lin1, (float4*)hA);

    tp_uuu_kernel<<<EDGESN * 8 / 256, 256>>>(hA, srcp, w2, hb);
    updateB_kernel<<<NGB, 288>>>((const float4*)hb, rowptr, hA, lin2, (float4*)hB);

    readout_kernel<<<(NODESN + 255) / 256, 256>>>(hB, out_w, out);
}